// round 1
// baseline (speedup 1.0000x reference)
#include <cuda_runtime.h>
#include <cuda_bf16.h>
#include <math.h>

// ---------------------------------------------------------------------------
// MLA forward, fp32 baseline.
// Pipeline:
//  1. g_qa   = x @ wq_a^T                      [4096,1536]
//  2. rmsnorm(g_qa) * q_norm_w   (in place)
//  3. g_q    = g_qa @ wq_b^T                   [4096,3072]  (= [4096,16,192])
//  4. g_kv   = x @ wkv_a^T                     [4096,576]
//  5. kv_process: g_kf[:, :512] = rmsnorm(g_kv[:, :512])*kv_norm_w
//                 g_kf[:,512:576] = rope(g_kv[:,512:576])
//  6. q_process:  g_qf[:,h,512:576] = rope(g_q[:,h,128:192])
//  7. g_qf[:,h,0:512] = q_nope @ wkvb[h,:128,:]    (batched over h)
//  8. g_scores[b,h,s,t] = SCALE * (g_qf . g_kf)    (batched over b,h)
//  9. softmax over t with mask[s,t] added
// 10. g_attno[b,s,h,:] = P @ g_kf[:, :512]         (batched over b,h)
// 11. g_o2[:, h*128:...] = g_attno @ wkvb[h,128:,:]^T  (batched over h)
// 12. out = g_o2 @ wo^T
// ---------------------------------------------------------------------------

#define DIM     2048
#define N_HEADS 16
#define Q_LORA  1536
#define KV_LORA 512
#define NOPE    128
#define ROPE    64
#define V_HEAD  128
#define QK_HEAD 192   // NOPE + ROPE
#define BATCH   2
#define SEQ     2048
#define ROWS    (BATCH * SEQ)           // 4096
#define QKD     (KV_LORA + ROPE)        // 576 (absorbed attention dim)
#define SCALE_F 0.0721687836487032f     // 192^-0.5
#define EPS_F   1e-6f

// ------------------------- scratch (device globals) -------------------------
__device__ float g_qa    [(size_t)ROWS * Q_LORA];                 //  25 MB
__device__ float g_q     [(size_t)ROWS * N_HEADS * QK_HEAD];      //  50 MB
__device__ float g_kv    [(size_t)ROWS * QKD];                    // 9.4 MB
__device__ float g_kf    [(size_t)ROWS * QKD];                    // 9.4 MB
__device__ float g_qf    [(size_t)ROWS * N_HEADS * QKD];          // 151 MB
__device__ float g_scores[(size_t)BATCH * N_HEADS * SEQ * SEQ];   // 537 MB
__device__ float g_attno [(size_t)ROWS * N_HEADS * KV_LORA];      // 134 MB
__device__ float g_o2    [(size_t)ROWS * DIM];                    //  34 MB

// --------------------------- generic tiled GEMM -----------------------------
// C[m,n] = alpha * sum_k A[m,k] * (BT ? B[n,k] : B[k,n])
// Batched via blockIdx.z = zo*inner + zi with independent pointer strides.
template <bool BT>
__global__ void __launch_bounds__(256)
gemm_tiled(const float* __restrict__ A, const float* __restrict__ B,
           float* __restrict__ C,
           int M, int N, int K, int lda, int ldb, int ldc,
           long sAo, long sAi, long sBo, long sBi, long sCo, long sCi,
           int inner, float alpha)
{
    const int z  = blockIdx.z;
    const int zo = z / inner, zi = z % inner;
    A += (long)zo * sAo + (long)zi * sAi;
    B += (long)zo * sBo + (long)zi * sBi;
    C += (long)zo * sCo + (long)zi * sCi;

    __shared__ float As[16][68];   // [k][m], row stride 272B (16B aligned)
    __shared__ float Bs[16][68];   // [k][n]

    const int tid = threadIdx.x;
    const int m0 = blockIdx.x * 64, n0 = blockIdx.y * 64;
    const int ty = tid / 16, tx = tid % 16;

    float acc[4][4];
#pragma unroll
    for (int i = 0; i < 4; i++)
#pragma unroll
        for (int j = 0; j < 4; j++) acc[i][j] = 0.f;

    for (int k0 = 0; k0 < K; k0 += 16) {
        // A tile: 64 rows x 16 k (k contiguous in gmem)
        {
            const int kk = tid % 16, mm = tid / 16;
#pragma unroll
            for (int r = 0; r < 4; r++) {
                const int m = mm + r * 16;
                float v = 0.f;
                if (m0 + m < M) v = A[(long)(m0 + m) * lda + (k0 + kk)];
                As[kk][m] = v;
            }
        }
        // B tile
        if (!BT) {
            const int nn = tid % 64, kk = tid / 64;
#pragma unroll
            for (int r = 0; r < 4; r++) {
                const int k = kk + r * 4;
                float v = 0.f;
                if (n0 + nn < N) v = B[(long)(k0 + k) * ldb + (n0 + nn)];
                Bs[k][nn] = v;
            }
        } else {
            const int kk = tid % 16, nn = tid / 16;
#pragma unroll
            for (int r = 0; r < 4; r++) {
                const int n = nn + r * 16;
                float v = 0.f;
                if (n0 + n < N) v = B[(long)(n0 + n) * ldb + (k0 + kk)];
                Bs[kk][n] = v;
            }
        }
        __syncthreads();

#pragma unroll
        for (int k = 0; k < 16; k++) {
            float a[4], b[4];
#pragma unroll
            for (int i = 0; i < 4; i++) a[i] = As[k][ty * 4 + i];
#pragma unroll
            for (int j = 0; j < 4; j++) b[j] = Bs[k][tx * 4 + j];
#pragma unroll
            for (int i = 0; i < 4; i++)
#pragma unroll
                for (int j = 0; j < 4; j++) acc[i][j] += a[i] * b[j];
        }
        __syncthreads();
    }

#pragma unroll
    for (int i = 0; i < 4; i++) {
        const int m = m0 + ty * 4 + i;
        if (m >= M) continue;
#pragma unroll
        for (int j = 0; j < 4; j++) {
            const int n = n0 + tx * 4 + j;
            if (n < N) C[(long)m * ldc + n] = alpha * acc[i][j];
        }
    }
}

// --------------------------- rmsnorm on g_qa --------------------------------
__global__ void __launch_bounds__(256)
rmsnorm_qa_kernel(const float* __restrict__ w)
{
    const long row = blockIdx.x;
    float* p = g_qa + row * Q_LORA;
    const int tid = threadIdx.x;

    float v[6];
    float ss = 0.f;
#pragma unroll
    for (int i = 0; i < 6; i++) {
        v[i] = p[tid + i * 256];
        ss += v[i] * v[i];
    }
    __shared__ float red[256];
    red[tid] = ss; __syncthreads();
    for (int o = 128; o > 0; o >>= 1) {
        if (tid < o) red[tid] += red[tid + o];
        __syncthreads();
    }
    const float scale = rsqrtf(red[0] / (float)Q_LORA + EPS_F);
#pragma unroll
    for (int i = 0; i < 6; i++)
        p[tid + i * 256] = v[i] * scale * w[tid + i * 256];
}

// ------------- kv_process: rmsnorm(c)*w -> kf[:512], rope(k_pe) -> kf[512:] --
__global__ void __launch_bounds__(256)
kv_process_kernel(const float* __restrict__ kv_norm_w,
                  const float* __restrict__ fcos,
                  const float* __restrict__ fsin)
{
    const long row = blockIdx.x;
    const int pos = (int)(row & (SEQ - 1));
    const float* src = g_kv + row * QKD;
    float*       dst = g_kf + row * QKD;
    const int tid = threadIdx.x;

    float v0 = src[tid], v1 = src[tid + 256];
    __shared__ float red[256];
    red[tid] = v0 * v0 + v1 * v1; __syncthreads();
    for (int o = 128; o > 0; o >>= 1) {
        if (tid < o) red[tid] += red[tid + o];
        __syncthreads();
    }
    const float scale = rsqrtf(red[0] / (float)KV_LORA + EPS_F);
    dst[tid]       = v0 * scale * kv_norm_w[tid];
    dst[tid + 256] = v1 * scale * kv_norm_w[tid + 256];

    if (tid < 32) {
        const float x0 = src[KV_LORA + 2 * tid];
        const float x1 = src[KV_LORA + 2 * tid + 1];
        const float c = fcos[pos * 32 + tid];
        const float s = fsin[pos * 32 + tid];
        dst[KV_LORA + 2 * tid]     = x0 * c - x1 * s;
        dst[KV_LORA + 2 * tid + 1] = x0 * s + x1 * c;
    }
}

// ------------- q_process: rope(q_pe[h]) -> qf[:,h,512:576] ------------------
__global__ void __launch_bounds__(512)
q_process_kernel(const float* __restrict__ fcos, const float* __restrict__ fsin)
{
    const long row = blockIdx.x;
    const int pos = (int)(row & (SEQ - 1));
    const int h = threadIdx.x / 32;
    const int i = threadIdx.x % 32;

    const float* src = g_q + row * (N_HEADS * QK_HEAD) + h * QK_HEAD + NOPE;
    float*       dst = g_qf + row * (N_HEADS * QKD) + h * QKD + KV_LORA;
    const float x0 = src[2 * i], x1 = src[2 * i + 1];
    const float c = fcos[pos * 32 + i];
    const float s = fsin[pos * 32 + i];
    dst[2 * i]     = x0 * c - x1 * s;
    dst[2 * i + 1] = x0 * s + x1 * c;
}

// ------------- softmax over t with causal mask ------------------------------
// One block per score row; row = (b*16 + h)*2048 + s
__global__ void __launch_bounds__(256)
softmax_mask_kernel(const float* __restrict__ mask)
{
    const long row = blockIdx.x;
    const int s = (int)(row & (SEQ - 1));
    float* p = g_scores + row * SEQ;
    const float* mrow = mask + (long)s * SEQ;
    const int tid = threadIdx.x;

    float v[8];
    float mx = -INFINITY;
#pragma unroll
    for (int i = 0; i < 8; i++) {
        const int t = tid + i * 256;
        v[i] = p[t] + mrow[t];
        mx = fmaxf(mx, v[i]);
    }
    __shared__ float red[256];
    red[tid] = mx; __syncthreads();
    for (int o = 128; o > 0; o >>= 1) {
        if (tid < o) red[tid] = fmaxf(red[tid], red[tid + o]);
        __syncthreads();
    }
    mx = red[0]; __syncthreads();

    float sum = 0.f;
#pragma unroll
    for (int i = 0; i < 8; i++) {
        v[i] = expf(v[i] - mx);
        sum += v[i];
    }
    red[tid] = sum; __syncthreads();
    for (int o = 128; o > 0; o >>= 1) {
        if (tid < o) red[tid] += red[tid + o];
        __syncthreads();
    }
    const float inv = 1.f / red[0];
#pragma unroll
    for (int i = 0; i < 8; i++) p[tid + i * 256] = v[i] * inv;
}

// ---------------------------------------------------------------------------
extern "C" void kernel_launch(void* const* d_in, const int* in_sizes, int n_in,
                              void* d_out, int out_size)
{
    const float* x         = (const float*)d_in[0];
    const float* fcos      = (const float*)d_in[1];
    const float* fsin      = (const float*)d_in[2];
    const float* mask      = (const float*)d_in[3];
    const float* wq_a      = (const float*)d_in[4];
    const float* q_norm_w  = (const float*)d_in[5];
    const float* wq_b      = (const float*)d_in[6];
    const float* wkv_a     = (const float*)d_in[7];
    const float* kv_norm_w = (const float*)d_in[8];
    const float* wkv_b     = (const float*)d_in[9];
    const float* wo        = (const float*)d_in[10];
    float* out = (float*)d_out;

    float *p_qa, *p_q, *p_kv, *p_kf, *p_qf, *p_sc, *p_at, *p_o2;
    cudaGetSymbolAddress((void**)&p_qa, g_qa);
    cudaGetSymbolAddress((void**)&p_q,  g_q);
    cudaGetSymbolAddress((void**)&p_kv, g_kv);
    cudaGetSymbolAddress((void**)&p_kf, g_kf);
    cudaGetSymbolAddress((void**)&p_qf, g_qf);
    cudaGetSymbolAddress((void**)&p_sc, g_scores);
    cudaGetSymbolAddress((void**)&p_at, g_attno);
    cudaGetSymbolAddress((void**)&p_o2, g_o2);

    dim3 blk(256);

    // 1. g_qa = x @ wq_a^T : [4096,1536] k=2048
    gemm_tiled<true><<<dim3(ROWS/64, Q_LORA/64, 1), blk>>>(
        x, wq_a, p_qa, ROWS, Q_LORA, DIM, DIM, DIM, Q_LORA,
        0,0, 0,0, 0,0, 1, 1.f);

    // 2. rmsnorm in place
    rmsnorm_qa_kernel<<<ROWS, blk>>>(q_norm_w);

    // 3. g_q = g_qa @ wq_b^T : [4096,3072] k=1536
    gemm_tiled<true><<<dim3(ROWS/64, (N_HEADS*QK_HEAD)/64, 1), blk>>>(
        p_qa, wq_b, p_q, ROWS, N_HEADS*QK_HEAD, Q_LORA, Q_LORA, Q_LORA, N_HEADS*QK_HEAD,
        0,0, 0,0, 0,0, 1, 1.f);

    // 4. g_kv = x @ wkv_a^T : [4096,576] k=2048
    gemm_tiled<true><<<dim3(ROWS/64, QKD/64, 1), blk>>>(
        x, wkv_a, p_kv, ROWS, QKD, DIM, DIM, DIM, QKD,
        0,0, 0,0, 0,0, 1, 1.f);

    // 5. kv -> kf (rmsnorm + rope)
    kv_process_kernel<<<ROWS, blk>>>(kv_norm_w, fcos, fsin);

    // 6. rope(q_pe) -> qf[...,512:576]
    q_process_kernel<<<ROWS, 512>>>(fcos, fsin);

    // 7. qf[...,0:512] = q_nope @ wkvb[h,:128,:]  (NN, batched over h)
    gemm_tiled<false><<<dim3(ROWS/64, KV_LORA/64, N_HEADS), blk>>>(
        p_q, wkv_b, p_qf, ROWS, KV_LORA, NOPE,
        N_HEADS*QK_HEAD, KV_LORA, N_HEADS*QKD,
        0, QK_HEAD,
        0, (long)(NOPE+V_HEAD)*KV_LORA,
        0, QKD,
        N_HEADS, 1.f);

    // 8. scores = SCALE * qf @ kf^T   (batched over b,h)
    gemm_tiled<true><<<dim3(SEQ/64, SEQ/64, BATCH*N_HEADS), blk>>>(
        p_qf, p_kf, p_sc, SEQ, SEQ, QKD,
        N_HEADS*QKD, QKD, SEQ,
        (long)SEQ*N_HEADS*QKD, QKD,
        (long)SEQ*QKD, 0,
        (long)N_HEADS*SEQ*SEQ, (long)SEQ*SEQ,
        N_HEADS, SCALE_F);

    // 9. softmax with mask
    softmax_mask_kernel<<<BATCH*N_HEADS*SEQ, blk>>>(mask);

    // 10. attno[b,s,h,:] = P @ kf[:, :512]  (NN, batched over b,h)
    gemm_tiled<false><<<dim3(SEQ/64, KV_LORA/64, BATCH*N_HEADS), blk>>>(
        p_sc, p_kf, p_at, SEQ, KV_LORA, SEQ,
        SEQ, QKD, N_HEADS*KV_LORA,
        (long)N_HEADS*SEQ*SEQ, (long)SEQ*SEQ,
        (long)SEQ*QKD, 0,
        (long)SEQ*N_HEADS*KV_LORA, KV_LORA,
        N_HEADS, 1.f);

    // 11. o2[:, h*128:(h+1)*128] = attno[:,h,:] @ wkvb[h,128:,:]^T (batched h)
    gemm_tiled<true><<<dim3(ROWS/64, V_HEAD/64, N_HEADS), blk>>>(
        p_at, wkv_b + (size_t)NOPE*KV_LORA, p_o2, ROWS, V_HEAD, KV_LORA,
        N_HEADS*KV_LORA, KV_LORA, DIM,
        0, KV_LORA,
        0, (long)(NOPE+V_HEAD)*KV_LORA,
        0, V_HEAD,
        N_HEADS, 1.f);

    // 12. out = o2 @ wo^T : [4096,2048] k=2048
    gemm_tiled<true><<<dim3(ROWS/64, DIM/64, 1), blk>>>(
        p_o2, wo, out, ROWS, DIM, DIM, DIM, DIM, DIM,
        0,0, 0,0, 0,0, 1, 1.f);
}

// round 4
// speedup vs baseline: 1.8938x; 1.8938x over previous
#include <cuda_runtime.h>
#include <cuda_bf16.h>
#include <math.h>
#include <stdint.h>

// ---------------------------------------------------------------------------
// MLA forward. mma.sync tf32 tensor-core GEMMs with 3xTF32 error compensation
// (hi/lo split: A.B ~= Ahi.Bhi + Ahi.Blo + Alo.Bhi) -> ~fp32 accuracy.
// PTX-stable on compute_103 (no tcgen05 -- rejected by ptxas on this harness).
// 128x128 CTA tile, BK=32, cp.async double-buffered smem, 8 warps (2x4),
// warp tile 64x32, m16n8k8 tf32 HMMA, fp32 accumulate.
// All GEMMs are C = alpha * A.B^T with K-major operands.
// ---------------------------------------------------------------------------

#define DIM     2048
#define N_HEADS 16
#define Q_LORA  1536
#define KV_LORA 512
#define NOPE    128
#define ROPE    64
#define V_HEAD  128
#define QK_HEAD 192
#define BATCH   2
#define SEQ     2048
#define ROWS    (BATCH * SEQ)
#define QKD     (KV_LORA + ROPE)        // 576
#define SCALE_F 0.0721687836487032f     // 192^-0.5
#define EPS_F   1e-6f

// ------------------------- scratch (device globals) -------------------------
__device__ __align__(256) float g_qa    [(size_t)ROWS * Q_LORA];
__device__ __align__(256) float g_q     [(size_t)ROWS * N_HEADS * QK_HEAD];
__device__ __align__(256) float g_kv    [(size_t)ROWS * QKD];
__device__ __align__(256) float g_kf    [(size_t)ROWS * QKD];
__device__ __align__(256) float g_qf    [(size_t)ROWS * N_HEADS * QKD];
__device__ __align__(256) float g_scores[(size_t)BATCH * N_HEADS * SEQ * SEQ];
__device__ __align__(256) float g_attno [(size_t)ROWS * N_HEADS * KV_LORA];
__device__ __align__(256) float g_o2    [(size_t)ROWS * DIM];
__device__ __align__(256) float g_vT    [(size_t)BATCH * KV_LORA * SEQ];
__device__ __align__(256) float g_wkvbT [(size_t)N_HEADS * KV_LORA * NOPE];

// ----------------------------- helpers --------------------------------------
__device__ __forceinline__ uint32_t smem_u32(const void* p) {
    uint32_t a;
    asm("{ .reg .u64 t; cvta.to.shared.u64 t, %1; cvt.u32.u64 %0, t; }"
        : "=r"(a) : "l"(p));
    return a;
}

__device__ __forceinline__ void cp16(uint32_t dst, const float* src) {
    asm volatile("cp.async.ca.shared.global [%0], [%1], 16;"
                 :: "r"(dst), "l"(src) : "memory");
}
#define CP_COMMIT() asm volatile("cp.async.commit_group;" ::: "memory")
#define CP_WAIT(n)  asm volatile("cp.async.wait_group %0;" :: "n"(n) : "memory")

__device__ __forceinline__ void mma_tf32(float* d, const uint32_t* a,
                                         const uint32_t* b) {
    asm volatile(
        "mma.sync.aligned.m16n8k8.row.col.f32.tf32.tf32.f32 "
        "{%0,%1,%2,%3}, {%4,%5,%6,%7}, {%8,%9}, {%0,%1,%2,%3};"
        : "+f"(d[0]), "+f"(d[1]), "+f"(d[2]), "+f"(d[3])
        : "r"(a[0]), "r"(a[1]), "r"(a[2]), "r"(a[3]), "r"(b[0]), "r"(b[1]));
}

// split fp32 -> (hi, lo) tf32 pair; hi + lo carries ~22 mantissa bits
__device__ __forceinline__ void tf32_split(float x, uint32_t& hi, uint32_t& lo) {
    uint32_t h;
    asm("cvt.rna.tf32.f32 %0, %1;" : "=r"(h) : "f"(x));
    float r = x - __uint_as_float(h);
    uint32_t l;
    asm("cvt.rna.tf32.f32 %0, %1;" : "=r"(l) : "f"(r));
    hi = h; lo = l;
}

// ----------------------- tensor-core GEMM (C = alpha*A.B^T) -----------------
// A[m,k] lda, B[n,k] ldb, both K-major, fp32. M%128==0, K%32==0, N arbitrary.
#define BK     32
#define ROWF   36                         // BK + 4 pad floats
#define TILE_F (128 * ROWF)               // floats per tile
#define TILE_B (TILE_F * 4)               // 18432 bytes
#define SMEM_BYTES (4 * TILE_B)           // A0,B0,A1,B1 = 73728

// load one 128 x 32 tile (rows >= limit zero-filled)
__device__ __forceinline__ void load_tile(uint32_t sbase,
                                          const float* __restrict__ src,
                                          int ld, int k0, int limit, int tid) {
#pragma unroll
    for (int it = 0; it < 4; it++) {
        const int c = tid + it * 256;
        const int row = c >> 3, q = c & 7;
        const uint32_t dst = sbase + (uint32_t)(row * ROWF + q * 4) * 4;
        if (row < limit) {
            cp16(dst, src + (size_t)row * ld + k0 + q * 4);
        } else {
            asm volatile("st.shared.v4.b32 [%0], {%1,%1,%1,%1};"
                         :: "r"(dst), "r"(0) : "memory");
        }
    }
}

__global__ void __launch_bounds__(256)
gemm_mma(const float* __restrict__ A, const float* __restrict__ B,
         float* __restrict__ C,
         int M, int N, int K, int lda, int ldb, int ldc,
         long sAo, long sAi, long sBo, long sBi, long sCo, long sCi,
         int inner, float alpha)
{
    extern __shared__ float smem[];
    const uint32_t sb = smem_u32(smem);
    const int tid = threadIdx.x, lane = tid & 31, wid = tid >> 5;
    const int wm = wid & 1, wn = wid >> 1;          // 2 x 4 warp grid
    const int g = lane >> 2, tig = lane & 3;

    const int z = blockIdx.z, zo = z / inner, zi = z - zo * inner;
    A += (long)zo * sAo + (long)zi * sAi;
    B += (long)zo * sBo + (long)zi * sBi;
    C += (long)zo * sCo + (long)zi * sCi;

    const int m0 = blockIdx.x * 128, n0 = blockIdx.y * 128;
    const float* At = A + (size_t)m0 * lda;
    const float* Bt = B + (size_t)n0 * ldb;
    const int nlim = min(128, N - n0);

    // smem: [A0][B0][A1][B1]
    const uint32_t aoff[2] = { sb,              sb + 2 * TILE_B };
    const uint32_t boff[2] = { sb + TILE_B,     sb + 3 * TILE_B };
    const float*  smemf = smem;

    float acc[4][4][4];
#pragma unroll
    for (int i = 0; i < 4; i++)
#pragma unroll
        for (int j = 0; j < 4; j++)
#pragma unroll
            for (int r = 0; r < 4; r++) acc[i][j][r] = 0.f;

    const int nch = K / BK;

    load_tile(aoff[0], At, lda, 0, 128, tid);
    load_tile(boff[0], Bt, ldb, 0, nlim, tid);
    CP_COMMIT();

    for (int c = 0; c < nch; c++) {
        if (c + 1 < nch) {
            load_tile(aoff[(c + 1) & 1], At, lda, (c + 1) * BK, 128, tid);
            load_tile(boff[(c + 1) & 1], Bt, ldb, (c + 1) * BK, nlim, tid);
            CP_COMMIT();
            CP_WAIT(1);
        } else {
            CP_WAIT(0);
        }
        __syncthreads();

        const float* Ab = smemf + (aoff[c & 1] - sb) / 4;
        const float* Bb = smemf + (boff[c & 1] - sb) / 4;

#pragma unroll
        for (int ks = 0; ks < BK; ks += 8) {
            uint32_t ah[4][4], al[4][4], bh[4][2], bl[4][2];
#pragma unroll
            for (int i = 0; i < 4; i++) {
                const int m = wm * 64 + i * 16 + g;
                const float* p = Ab + m * ROWF + ks + tig;
                tf32_split(p[0],            ah[i][0], al[i][0]);
                tf32_split(p[8 * ROWF],     ah[i][1], al[i][1]);
                tf32_split(p[4],            ah[i][2], al[i][2]);
                tf32_split(p[8 * ROWF + 4], ah[i][3], al[i][3]);
            }
#pragma unroll
            for (int j = 0; j < 4; j++) {
                const int n = wn * 32 + j * 8 + g;
                const float* p = Bb + n * ROWF + ks + tig;
                tf32_split(p[0], bh[j][0], bl[j][0]);
                tf32_split(p[4], bh[j][1], bl[j][1]);
            }
#pragma unroll
            for (int i = 0; i < 4; i++)
#pragma unroll
                for (int j = 0; j < 4; j++) {
                    mma_tf32(acc[i][j], al[i], bh[j]);   // cross terms first
                    mma_tf32(acc[i][j], ah[i], bl[j]);
                    mma_tf32(acc[i][j], ah[i], bh[j]);   // dominant term
                }
        }
        __syncthreads();
    }

    // epilogue
#pragma unroll
    for (int i = 0; i < 4; i++) {
        const int r0 = m0 + wm * 64 + i * 16 + g;
#pragma unroll
        for (int j = 0; j < 4; j++) {
            const int col = n0 + wn * 32 + j * 8 + tig * 2;
            if (col + 1 < N) {
                float2 v0 = make_float2(alpha * acc[i][j][0], alpha * acc[i][j][1]);
                float2 v1 = make_float2(alpha * acc[i][j][2], alpha * acc[i][j][3]);
                *reinterpret_cast<float2*>(C + (size_t)r0 * ldc + col) = v0;
                *reinterpret_cast<float2*>(C + (size_t)(r0 + 8) * ldc + col) = v1;
            } else if (col < N) {
                C[(size_t)r0 * ldc + col]       = alpha * acc[i][j][0];
                C[(size_t)(r0 + 8) * ldc + col] = alpha * acc[i][j][2];
            }
        }
    }
}

// ------------------------- 32x32 transpose, batched -------------------------
__global__ void __launch_bounds__(256)
transpose_k(const float* __restrict__ src, float* __restrict__ dst,
            int lds, int ldd, long sS, long sD)
{
    __shared__ float t[32][33];
    const int z = blockIdx.z;
    src += (long)z * sS; dst += (long)z * sD;
    const int r0 = blockIdx.x * 32, c0 = blockIdx.y * 32;
    const int tx = threadIdx.x, ty = threadIdx.y;
#pragma unroll
    for (int i = 0; i < 4; i++)
        t[ty + 8 * i][tx] = src[(long)(r0 + ty + 8 * i) * lds + c0 + tx];
    __syncthreads();
#pragma unroll
    for (int i = 0; i < 4; i++)
        dst[(long)(c0 + ty + 8 * i) * ldd + r0 + tx] = t[tx][ty + 8 * i];
}

// --------------------------- rmsnorm on g_qa --------------------------------
__global__ void __launch_bounds__(256)
rmsnorm_qa_kernel(const float* __restrict__ w)
{
    const long row = blockIdx.x;
    float* p = g_qa + row * Q_LORA;
    const int tid = threadIdx.x;
    float v[6];
    float ss = 0.f;
#pragma unroll
    for (int i = 0; i < 6; i++) { v[i] = p[tid + i * 256]; ss += v[i] * v[i]; }
    __shared__ float red[256];
    red[tid] = ss; __syncthreads();
    for (int o = 128; o > 0; o >>= 1) {
        if (tid < o) red[tid] += red[tid + o];
        __syncthreads();
    }
    const float scale = rsqrtf(red[0] / (float)Q_LORA + EPS_F);
#pragma unroll
    for (int i = 0; i < 6; i++)
        p[tid + i * 256] = v[i] * scale * w[tid + i * 256];
}

// ------------- kv_process ---------------------------------------------------
__global__ void __launch_bounds__(256)
kv_process_kernel(const float* __restrict__ kv_norm_w,
                  const float* __restrict__ fcos,
                  const float* __restrict__ fsin)
{
    const long row = blockIdx.x;
    const int pos = (int)(row & (SEQ - 1));
    const float* src = g_kv + row * QKD;
    float*       dst = g_kf + row * QKD;
    const int tid = threadIdx.x;

    float v0 = src[tid], v1 = src[tid + 256];
    __shared__ float red[256];
    red[tid] = v0 * v0 + v1 * v1; __syncthreads();
    for (int o = 128; o > 0; o >>= 1) {
        if (tid < o) red[tid] += red[tid + o];
        __syncthreads();
    }
    const float scale = rsqrtf(red[0] / (float)KV_LORA + EPS_F);
    dst[tid]       = v0 * scale * kv_norm_w[tid];
    dst[tid + 256] = v1 * scale * kv_norm_w[tid + 256];

    if (tid < 32) {
        const float x0 = src[KV_LORA + 2 * tid];
        const float x1 = src[KV_LORA + 2 * tid + 1];
        const float c = fcos[pos * 32 + tid];
        const float s = fsin[pos * 32 + tid];
        dst[KV_LORA + 2 * tid]     = x0 * c - x1 * s;
        dst[KV_LORA + 2 * tid + 1] = x0 * s + x1 * c;
    }
}

// ------------- q_process ----------------------------------------------------
__global__ void __launch_bounds__(512)
q_process_kernel(const float* __restrict__ fcos, const float* __restrict__ fsin)
{
    const long row = blockIdx.x;
    const int pos = (int)(row & (SEQ - 1));
    const int h = threadIdx.x / 32;
    const int i = threadIdx.x % 32;

    const float* src = g_q + row * (N_HEADS * QK_HEAD) + h * QK_HEAD + NOPE;
    float*       dst = g_qf + row * (N_HEADS * QKD) + h * QKD + KV_LORA;
    const float x0 = src[2 * i], x1 = src[2 * i + 1];
    const float c = fcos[pos * 32 + i];
    const float s = fsin[pos * 32 + i];
    dst[2 * i]     = x0 * c - x1 * s;
    dst[2 * i + 1] = x0 * s + x1 * c;
}

// ------------- softmax over t with causal mask ------------------------------
__global__ void __launch_bounds__(256)
softmax_mask_kernel(const float* __restrict__ mask)
{
    const long row = blockIdx.x;
    const int s = (int)(row & (SEQ - 1));
    float* p = g_scores + row * SEQ;
    const float* mrow = mask + (long)s * SEQ;
    const int tid = threadIdx.x;

    float v[8];
    float mx = -INFINITY;
#pragma unroll
    for (int i = 0; i < 8; i++) {
        const int t = tid + i * 256;
        v[i] = p[t] + mrow[t];
        mx = fmaxf(mx, v[i]);
    }
    __shared__ float red[256];
    red[tid] = mx; __syncthreads();
    for (int o = 128; o > 0; o >>= 1) {
        if (tid < o) red[tid] = fmaxf(red[tid], red[tid + o]);
        __syncthreads();
    }
    mx = red[0]; __syncthreads();

    float sum = 0.f;
#pragma unroll
    for (int i = 0; i < 8; i++) { v[i] = expf(v[i] - mx); sum += v[i]; }
    red[tid] = sum; __syncthreads();
    for (int o = 128; o > 0; o >>= 1) {
        if (tid < o) red[tid] += red[tid + o];
        __syncthreads();
    }
    const float inv = 1.f / red[0];
#pragma unroll
    for (int i = 0; i < 8; i++) p[tid + i * 256] = v[i] * inv;
}

// ---------------------------------------------------------------------------
extern "C" void kernel_launch(void* const* d_in, const int* in_sizes, int n_in,
                              void* d_out, int out_size)
{
    const float* x         = (const float*)d_in[0];
    const float* fcos      = (const float*)d_in[1];
    const float* fsin      = (const float*)d_in[2];
    const float* mask      = (const float*)d_in[3];
    const float* wq_a      = (const float*)d_in[4];
    const float* q_norm_w  = (const float*)d_in[5];
    const float* wq_b      = (const float*)d_in[6];
    const float* wkv_a     = (const float*)d_in[7];
    const float* kv_norm_w = (const float*)d_in[8];
    const float* wkv_b     = (const float*)d_in[9];
    const float* wo        = (const float*)d_in[10];
    float* out = (float*)d_out;

    float *p_qa, *p_q, *p_kv, *p_kf, *p_qf, *p_sc, *p_at, *p_o2, *p_vT, *p_wT;
    cudaGetSymbolAddress((void**)&p_qa, g_qa);
    cudaGetSymbolAddress((void**)&p_q,  g_q);
    cudaGetSymbolAddress((void**)&p_kv, g_kv);
    cudaGetSymbolAddress((void**)&p_kf, g_kf);
    cudaGetSymbolAddress((void**)&p_qf, g_qf);
    cudaGetSymbolAddress((void**)&p_sc, g_scores);
    cudaGetSymbolAddress((void**)&p_at, g_attno);
    cudaGetSymbolAddress((void**)&p_o2, g_o2);
    cudaGetSymbolAddress((void**)&p_vT, g_vT);
    cudaGetSymbolAddress((void**)&p_wT, g_wkvbT);

    cudaFuncSetAttribute(gemm_mma, cudaFuncAttributeMaxDynamicSharedMemorySize,
                         SMEM_BYTES);

    dim3 blk(256);
    dim3 tb(32, 8);

    // 1. qa = x @ wq_a^T  [4096,1536] K=2048
    gemm_mma<<<dim3(ROWS/128, Q_LORA/128, 1), blk, SMEM_BYTES>>>(
        x, wq_a, p_qa, ROWS, Q_LORA, DIM, DIM, DIM, Q_LORA,
        0,0, 0,0, 0,0, 1, 1.f);

    // 2. rmsnorm in place
    rmsnorm_qa_kernel<<<ROWS, blk>>>(q_norm_w);

    // 3. q = qa @ wq_b^T  [4096,3072] K=1536
    gemm_mma<<<dim3(ROWS/128, (N_HEADS*QK_HEAD)/128, 1), blk, SMEM_BYTES>>>(
        p_qa, wq_b, p_q, ROWS, N_HEADS*QK_HEAD, Q_LORA,
        Q_LORA, Q_LORA, N_HEADS*QK_HEAD, 0,0, 0,0, 0,0, 1, 1.f);

    // 4. kv = x @ wkv_a^T  [4096,576] K=2048
    gemm_mma<<<dim3(ROWS/128, (QKD + 127)/128, 1), blk, SMEM_BYTES>>>(
        x, wkv_a, p_kv, ROWS, QKD, DIM, DIM, DIM, QKD,
        0,0, 0,0, 0,0, 1, 1.f);

    // 5. kv -> kf (rmsnorm + rope)
    kv_process_kernel<<<ROWS, blk>>>(kv_norm_w, fcos, fsin);

    // 6. rope(q_pe) -> qf[...,512:576]
    q_process_kernel<<<ROWS, 512>>>(fcos, fsin);

    // 6b. vT[b][c][t] = kf[b*2048+t][c]  (c < 512)
    transpose_k<<<dim3(SEQ/32, KV_LORA/32, BATCH), tb>>>(
        p_kf, p_vT, QKD, SEQ, (long)SEQ*QKD, (long)KV_LORA*SEQ);
    // 6c. wkvbT[h][c][d] = wkv_b[h*256+d][c]  (d < 128)
    transpose_k<<<dim3(NOPE/32, KV_LORA/32, N_HEADS), tb>>>(
        wkv_b, p_wT, KV_LORA, NOPE, (long)(NOPE+V_HEAD)*KV_LORA, (long)KV_LORA*NOPE);

    // 7. qf[...,0:512] = q_nope @ wkvbT[h]^T  (batched h) K=128
    gemm_mma<<<dim3(ROWS/128, KV_LORA/128, N_HEADS), blk, SMEM_BYTES>>>(
        p_q, p_wT, p_qf, ROWS, KV_LORA, NOPE,
        N_HEADS*QK_HEAD, NOPE, N_HEADS*QKD,
        0, QK_HEAD, 0, (long)KV_LORA*NOPE, 0, QKD, N_HEADS, 1.f);

    // 8. scores = SCALE * qf @ kf^T  (batched b,h) K=576
    gemm_mma<<<dim3(SEQ/128, SEQ/128, BATCH*N_HEADS), blk, SMEM_BYTES>>>(
        p_qf, p_kf, p_sc, SEQ, SEQ, QKD,
        N_HEADS*QKD, QKD, SEQ,
        (long)SEQ*N_HEADS*QKD, QKD,
        (long)SEQ*QKD, 0,
        (long)N_HEADS*SEQ*SEQ, (long)SEQ*SEQ,
        N_HEADS, SCALE_F);

    // 9. softmax with mask
    softmax_mask_kernel<<<BATCH*N_HEADS*SEQ, blk>>>(mask);

    // 10. attno = P @ vT^T  (batched b,h) K=2048
    gemm_mma<<<dim3(SEQ/128, KV_LORA/128, BATCH*N_HEADS), blk, SMEM_BYTES>>>(
        p_sc, p_vT, p_at, SEQ, KV_LORA, SEQ,
        SEQ, SEQ, N_HEADS*KV_LORA,
        (long)N_HEADS*SEQ*SEQ, (long)SEQ*SEQ,
        (long)KV_LORA*SEQ, 0,
        (long)SEQ*N_HEADS*KV_LORA, KV_LORA,
        N_HEADS, 1.f);

    // 11. o2[:, h*128:(h+1)*128] = attno[:,h,:] @ wkvb_v^T  (batched h) K=512
    gemm_mma<<<dim3(ROWS/128, V_HEAD/128, N_HEADS), blk, SMEM_BYTES>>>(
        p_at, wkv_b + (size_t)NOPE*KV_LORA, p_o2, ROWS, V_HEAD, KV_LORA,
        N_HEADS*KV_LORA, KV_LORA, DIM,
        0, KV_LORA,
        0, (long)(NOPE+V_HEAD)*KV_LORA,
        0, V_HEAD, N_HEADS, 1.f);

    // 12. out = o2 @ wo^T  [4096,2048] K=2048
    gemm_mma<<<dim3(ROWS/128, DIM/128, 1), blk, SMEM_BYTES>>>(
        p_o2, wo, out, ROWS, DIM, DIM, DIM, DIM, DIM,
        0,0, 0,0, 0,0, 1, 1.f);
}

// round 5
// speedup vs baseline: 3.4781x; 1.8365x over previous
#include <cuda_runtime.h>
#include <cuda_bf16.h>
#include <math.h>
#include <stdint.h>

// ---------------------------------------------------------------------------
// MLA forward. Split-bf16 3-term tensor-core GEMMs:
//   x = hi + lo (two bf16), A.B ~= Ah.Bh + Ah.Bl + Al.Bh  (~17-bit mantissa)
// All operands pre-split to bf16 hi/lo in gmem (fused into producer epilogues).
// GEMM: 128x128 CTA tile, BK=32 (2 x k16), cp.async double-buffered, 8 warps
// (2x4), warp tile 64x32, ldmatrix fragment loads, m16n8k16 bf16 HMMA.
// PTX-stable on compute_103 (no tcgen05).
// ---------------------------------------------------------------------------

#define DIM     2048
#define N_HEADS 16
#define Q_LORA  1536
#define KV_LORA 512
#define NOPE    128
#define ROPE    64
#define V_HEAD  128
#define QK_HEAD 192
#define BATCH   2
#define SEQ     2048
#define ROWS    (BATCH * SEQ)
#define QKD     (KV_LORA + ROPE)        // 576
#define SCALE_F 0.0721687836487032f
#define EPS_F   1e-6f

typedef __nv_bfloat16 bf16;

// ------------------------- scratch (device globals) -------------------------
// bf16 hi/lo pairs for every GEMM operand
__device__ __align__(256) bf16  g_xh   [(size_t)ROWS * DIM];
__device__ __align__(256) bf16  g_xl   [(size_t)ROWS * DIM];
__device__ __align__(256) bf16  g_wqah [(size_t)Q_LORA * DIM];
__device__ __align__(256) bf16  g_wqal [(size_t)Q_LORA * DIM];
__device__ __align__(256) bf16  g_wqbh [(size_t)N_HEADS * QK_HEAD * Q_LORA];
__device__ __align__(256) bf16  g_wqbl [(size_t)N_HEADS * QK_HEAD * Q_LORA];
__device__ __align__(256) bf16  g_wkvah[(size_t)QKD * DIM];
__device__ __align__(256) bf16  g_wkval[(size_t)QKD * DIM];
__device__ __align__(256) bf16  g_wkvbh[(size_t)N_HEADS * 256 * KV_LORA];
__device__ __align__(256) bf16  g_wkvbl[(size_t)N_HEADS * 256 * KV_LORA];
__device__ __align__(256) bf16  g_woh  [(size_t)DIM * DIM];
__device__ __align__(256) bf16  g_wol  [(size_t)DIM * DIM];

__device__ __align__(256) float g_qa_f [(size_t)ROWS * Q_LORA];
__device__ __align__(256) bf16  g_qah  [(size_t)ROWS * Q_LORA];
__device__ __align__(256) bf16  g_qal  [(size_t)ROWS * Q_LORA];
__device__ __align__(256) bf16  g_qh   [(size_t)ROWS * N_HEADS * QK_HEAD];
__device__ __align__(256) bf16  g_ql   [(size_t)ROWS * N_HEADS * QK_HEAD];
__device__ __align__(256) float g_kv_f [(size_t)ROWS * QKD];
__device__ __align__(256) bf16  g_kfh  [(size_t)ROWS * QKD];
__device__ __align__(256) bf16  g_kfl  [(size_t)ROWS * QKD];
__device__ __align__(256) bf16  g_vTh  [(size_t)BATCH * KV_LORA * SEQ];
__device__ __align__(256) bf16  g_vTl  [(size_t)BATCH * KV_LORA * SEQ];
__device__ __align__(256) bf16  g_wTh  [(size_t)N_HEADS * KV_LORA * NOPE];
__device__ __align__(256) bf16  g_wTl  [(size_t)N_HEADS * KV_LORA * NOPE];
__device__ __align__(256) bf16  g_qfh  [(size_t)ROWS * N_HEADS * QKD];
__device__ __align__(256) bf16  g_qfl  [(size_t)ROWS * N_HEADS * QKD];
__device__ __align__(256) float g_sc   [(size_t)BATCH * N_HEADS * SEQ * SEQ];
__device__ __align__(256) bf16  g_Ph   [(size_t)BATCH * N_HEADS * SEQ * SEQ];
__device__ __align__(256) bf16  g_Pl   [(size_t)BATCH * N_HEADS * SEQ * SEQ];
__device__ __align__(256) bf16  g_ath  [(size_t)ROWS * N_HEADS * KV_LORA];
__device__ __align__(256) bf16  g_atl  [(size_t)ROWS * N_HEADS * KV_LORA];
__device__ __align__(256) bf16  g_o2h  [(size_t)ROWS * DIM];
__device__ __align__(256) bf16  g_o2l  [(size_t)ROWS * DIM];

// ----------------------------- helpers --------------------------------------
__device__ __forceinline__ uint32_t smem_u32(const void* p) {
    uint32_t a;
    asm("{ .reg .u64 t; cvta.to.shared.u64 t, %1; cvt.u32.u64 %0, t; }"
        : "=r"(a) : "l"(p));
    return a;
}
__device__ __forceinline__ void cp16(uint32_t dst, const void* src) {
    asm volatile("cp.async.ca.shared.global [%0], [%1], 16;"
                 :: "r"(dst), "l"(src) : "memory");
}
#define CP_COMMIT() asm volatile("cp.async.commit_group;" ::: "memory")
#define CP_WAIT(n)  asm volatile("cp.async.wait_group %0;" :: "n"(n) : "memory")

__device__ __forceinline__ void ldm_x4(uint32_t* r, uint32_t addr) {
    asm volatile("ldmatrix.sync.aligned.m8n8.x4.shared.b16 {%0,%1,%2,%3}, [%4];"
                 : "=r"(r[0]), "=r"(r[1]), "=r"(r[2]), "=r"(r[3]) : "r"(addr));
}
__device__ __forceinline__ void mma_bf16(float* d, const uint32_t* a,
                                         const uint32_t* b) {
    asm volatile(
        "mma.sync.aligned.m16n8k16.row.col.f32.bf16.bf16.f32 "
        "{%0,%1,%2,%3}, {%4,%5,%6,%7}, {%8,%9}, {%0,%1,%2,%3};"
        : "+f"(d[0]), "+f"(d[1]), "+f"(d[2]), "+f"(d[3])
        : "r"(a[0]), "r"(a[1]), "r"(a[2]), "r"(a[3]), "r"(b[0]), "r"(b[1]));
}
__device__ __forceinline__ void bsplit(float x, bf16& h, bf16& l) {
    h = __float2bfloat16_rn(x);
    l = __float2bfloat16_rn(x - __bfloat162float(h));
}

// ----------------------- GEMM: C = alpha * A.B^T ----------------------------
// A,B pre-split bf16 hi/lo, K-major. M%128==0, K%32==0, N arbitrary.
// OUTM=0: C f32.  OUTM=1: C split into Ch/Cl bf16.
#define ROWB 80                      // 64B data + 16B pad per smem row
#define TILE_BYTES (128 * ROWB)      // 10240
#define STAGE_BYTES (4 * TILE_BYTES) // Ah,Al,Bh,Bl
#define SMEM_BYTES (2 * STAGE_BYTES) // 81920

__device__ __forceinline__ void load_tile_bf(uint32_t dst, const bf16* __restrict__ src,
                                             int ld, int k0, int limit, int tid) {
#pragma unroll
    for (int it = 0; it < 2; it++) {
        const int idx = tid + it * 256;
        const int row = idx >> 2, seg = idx & 3;
        const uint32_t d = dst + (uint32_t)(row * ROWB + seg * 16);
        if (row < limit) {
            cp16(d, src + (size_t)row * ld + k0 + seg * 8);
        } else {
            asm volatile("st.shared.v4.b32 [%0], {%1,%1,%1,%1};"
                         :: "r"(d), "r"(0) : "memory");
        }
    }
}

template <int OUTM>
__global__ void __launch_bounds__(256)
gemm_bf3(const bf16* __restrict__ Ah, const bf16* __restrict__ Al,
         const bf16* __restrict__ Bh, const bf16* __restrict__ Bl,
         float* __restrict__ C, bf16* __restrict__ Ch, bf16* __restrict__ Cl,
         int M, int N, int K, int lda, int ldb, int ldc,
         long sAo, long sAi, long sBo, long sBi, long sCo, long sCi,
         int inner, float alpha)
{
    extern __shared__ char smem[];
    const uint32_t sb = smem_u32(smem);
    const int tid = threadIdx.x, lane = tid & 31, wid = tid >> 5;
    const int wm = wid & 1, wn = wid >> 1;
    const int g = lane >> 2, tig = lane & 3;

    const int z = blockIdx.z, zo = z / inner, zi = z - zo * inner;
    const long ofAB = (long)zo * sAo + (long)zi * sAi;
    const long ofB  = (long)zo * sBo + (long)zi * sBi;
    const long ofC  = (long)zo * sCo + (long)zi * sCi;
    Ah += ofAB; Al += ofAB;
    Bh += ofB;  Bl += ofB;

    const int m0 = blockIdx.x * 128, n0 = blockIdx.y * 128;
    const bf16* Ath = Ah + (size_t)m0 * lda;
    const bf16* Atl = Al + (size_t)m0 * lda;
    const bf16* Bth = Bh + (size_t)n0 * ldb;
    const bf16* Btl = Bl + (size_t)n0 * ldb;
    const int nlim = min(128, N - n0);

    float acc[4][4][4];
#pragma unroll
    for (int i = 0; i < 4; i++)
#pragma unroll
        for (int j = 0; j < 4; j++)
#pragma unroll
            for (int r = 0; r < 4; r++) acc[i][j][r] = 0.f;

    const int nch = K >> 5;

    load_tile_bf(sb + 0 * TILE_BYTES, Ath, lda, 0, 128, tid);
    load_tile_bf(sb + 1 * TILE_BYTES, Atl, lda, 0, 128, tid);
    load_tile_bf(sb + 2 * TILE_BYTES, Bth, ldb, 0, nlim, tid);
    load_tile_bf(sb + 3 * TILE_BYTES, Btl, ldb, 0, nlim, tid);
    CP_COMMIT();

    // lane-dependent ldmatrix base offsets (within a stage)
    const uint32_t aoffL = (uint32_t)((wm * 64 + (lane & 15)) * ROWB + (lane >> 4) * 16);
    const uint32_t boffL = (uint32_t)((wn * 32 + ((lane >> 4) & 1) * 8 + (lane & 7)) * ROWB
                                      + ((lane >> 3) & 1) * 16);

    for (int c = 0; c < nch; c++) {
        if (c + 1 < nch) {
            const uint32_t nb = sb + ((c + 1) & 1) * STAGE_BYTES;
            load_tile_bf(nb + 0 * TILE_BYTES, Ath, lda, (c + 1) << 5, 128, tid);
            load_tile_bf(nb + 1 * TILE_BYTES, Atl, lda, (c + 1) << 5, 128, tid);
            load_tile_bf(nb + 2 * TILE_BYTES, Bth, ldb, (c + 1) << 5, nlim, tid);
            load_tile_bf(nb + 3 * TILE_BYTES, Btl, ldb, (c + 1) << 5, nlim, tid);
            CP_COMMIT();
            CP_WAIT(1);
        } else {
            CP_WAIT(0);
        }
        __syncthreads();

        const uint32_t base = sb + (c & 1) * STAGE_BYTES;
        const uint32_t aA = base + aoffL;
        const uint32_t bA = base + 2 * TILE_BYTES + boffL;

#pragma unroll
        for (int ks = 0; ks < 2; ks++) {
            uint32_t ah[4][4], al[4][4], bh[2][4], bl[2][4];
#pragma unroll
            for (int i = 0; i < 4; i++) {
                ldm_x4(ah[i], aA + ks * 32 + i * 16 * ROWB);
                ldm_x4(al[i], aA + TILE_BYTES + ks * 32 + i * 16 * ROWB);
            }
#pragma unroll
            for (int jj = 0; jj < 2; jj++) {
                ldm_x4(bh[jj], bA + ks * 32 + jj * 16 * ROWB);
                ldm_x4(bl[jj], bA + TILE_BYTES + ks * 32 + jj * 16 * ROWB);
            }
#pragma unroll
            for (int i = 0; i < 4; i++)
#pragma unroll
                for (int j = 0; j < 4; j++) {
                    const uint32_t* bhp = &bh[j >> 1][(j & 1) * 2];
                    const uint32_t* blp = &bl[j >> 1][(j & 1) * 2];
                    mma_bf16(acc[i][j], al[i], bhp);
                    mma_bf16(acc[i][j], ah[i], blp);
                    mma_bf16(acc[i][j], ah[i], bhp);
                }
        }
        __syncthreads();
    }

    // epilogue
#pragma unroll
    for (int i = 0; i < 4; i++) {
        const int r0 = m0 + wm * 64 + i * 16 + g;
#pragma unroll
        for (int j = 0; j < 4; j++) {
            const int col = n0 + wn * 32 + j * 8 + tig * 2;
            if (col >= N) continue;
            const float c0 = alpha * acc[i][j][0], c1 = alpha * acc[i][j][1];
            const float c2 = alpha * acc[i][j][2], c3 = alpha * acc[i][j][3];
            if (OUTM == 0) {
                float* p0 = C + ofC + (size_t)r0 * ldc + col;
                float* p1 = C + ofC + (size_t)(r0 + 8) * ldc + col;
                if (col + 1 < N) {
                    *reinterpret_cast<float2*>(p0) = make_float2(c0, c1);
                    *reinterpret_cast<float2*>(p1) = make_float2(c2, c3);
                } else { p0[0] = c0; p1[0] = c2; }
            } else {
                bf16 h0, l0, h1, l1, h2, l2, h3, l3;
                bsplit(c0, h0, l0); bsplit(c1, h1, l1);
                bsplit(c2, h2, l2); bsplit(c3, h3, l3);
                __nv_bfloat162* ph0 = reinterpret_cast<__nv_bfloat162*>(
                    Ch + ofC + (size_t)r0 * ldc + col);
                __nv_bfloat162* pl0 = reinterpret_cast<__nv_bfloat162*>(
                    Cl + ofC + (size_t)r0 * ldc + col);
                __nv_bfloat162* ph1 = reinterpret_cast<__nv_bfloat162*>(
                    Ch + ofC + (size_t)(r0 + 8) * ldc + col);
                __nv_bfloat162* pl1 = reinterpret_cast<__nv_bfloat162*>(
                    Cl + ofC + (size_t)(r0 + 8) * ldc + col);
                *ph0 = __nv_bfloat162(h0, h1); *pl0 = __nv_bfloat162(l0, l1);
                *ph1 = __nv_bfloat162(h2, h3); *pl1 = __nv_bfloat162(l2, l3);
            }
        }
    }
}

// ---------------------- elementwise split f32 -> bf16 hi/lo ------------------
__global__ void __launch_bounds__(256)
split_kernel(const float* __restrict__ src, bf16* __restrict__ h,
             bf16* __restrict__ l, long n4)
{
    const long stride = (long)gridDim.x * blockDim.x;
    for (long i = blockIdx.x * (long)blockDim.x + threadIdx.x; i < n4; i += stride) {
        const float4 v = reinterpret_cast<const float4*>(src)[i];
        bf16 h0, l0, h1, l1, h2, l2, h3, l3;
        bsplit(v.x, h0, l0); bsplit(v.y, h1, l1);
        bsplit(v.z, h2, l2); bsplit(v.w, h3, l3);
        reinterpret_cast<__nv_bfloat162*>(h)[i * 2]     = __nv_bfloat162(h0, h1);
        reinterpret_cast<__nv_bfloat162*>(h)[i * 2 + 1] = __nv_bfloat162(h2, h3);
        reinterpret_cast<__nv_bfloat162*>(l)[i * 2]     = __nv_bfloat162(l0, l1);
        reinterpret_cast<__nv_bfloat162*>(l)[i * 2 + 1] = __nv_bfloat162(l2, l3);
    }
}

// ------------------- dual bf16 transpose (32x32 tiles) ----------------------
__global__ void __launch_bounds__(256)
transpose_bf2(const bf16* __restrict__ sh, const bf16* __restrict__ sl,
              bf16* __restrict__ dh, bf16* __restrict__ dl,
              int lds, int ldd, long sS, long sD)
{
    __shared__ float th[32][33], tl[32][33];
    const int z = blockIdx.z;
    sh += (long)z * sS; sl += (long)z * sS;
    dh += (long)z * sD; dl += (long)z * sD;
    const int r0 = blockIdx.x * 32, c0 = blockIdx.y * 32;
    const int tx = threadIdx.x, ty = threadIdx.y;
#pragma unroll
    for (int i = 0; i < 4; i++) {
        const long s = (long)(r0 + ty + 8 * i) * lds + c0 + tx;
        th[ty + 8 * i][tx] = __bfloat162float(sh[s]);
        tl[ty + 8 * i][tx] = __bfloat162float(sl[s]);
    }
    __syncthreads();
#pragma unroll
    for (int i = 0; i < 4; i++) {
        const long d = (long)(c0 + ty + 8 * i) * ldd + r0 + tx;
        dh[d] = __float2bfloat16_rn(th[tx][ty + 8 * i]);
        dl[d] = __float2bfloat16_rn(tl[tx][ty + 8 * i]);
    }
}

// --------------------------- rmsnorm: f32 -> split --------------------------
__global__ void __launch_bounds__(256)
rmsnorm_qa_kernel(const float* __restrict__ w)
{
    const long row = blockIdx.x;
    const float* p = g_qa_f + row * Q_LORA;
    const int tid = threadIdx.x;
    float v[6];
    float ss = 0.f;
#pragma unroll
    for (int i = 0; i < 6; i++) { v[i] = p[tid + i * 256]; ss += v[i] * v[i]; }
    __shared__ float red[256];
    red[tid] = ss; __syncthreads();
    for (int o = 128; o > 0; o >>= 1) {
        if (tid < o) red[tid] += red[tid + o];
        __syncthreads();
    }
    const float scale = rsqrtf(red[0] / (float)Q_LORA + EPS_F);
#pragma unroll
    for (int i = 0; i < 6; i++) {
        const int c = tid + i * 256;
        bf16 h, l;
        bsplit(v[i] * scale * w[c], h, l);
        g_qah[row * Q_LORA + c] = h;
        g_qal[row * Q_LORA + c] = l;
    }
}

// ------------- kv_process: f32 kv -> split kf (norm + rope) -----------------
__global__ void __launch_bounds__(256)
kv_process_kernel(const float* __restrict__ kv_norm_w,
                  const float* __restrict__ fcos,
                  const float* __restrict__ fsin)
{
    const long row = blockIdx.x;
    const int pos = (int)(row & (SEQ - 1));
    const float* src = g_kv_f + row * QKD;
    const int tid = threadIdx.x;

    const float v0 = src[tid], v1 = src[tid + 256];
    __shared__ float red[256];
    red[tid] = v0 * v0 + v1 * v1; __syncthreads();
    for (int o = 128; o > 0; o >>= 1) {
        if (tid < o) red[tid] += red[tid + o];
        __syncthreads();
    }
    const float scale = rsqrtf(red[0] / (float)KV_LORA + EPS_F);
    bf16 h, l;
    bsplit(v0 * scale * kv_norm_w[tid], h, l);
    g_kfh[row * QKD + tid] = h; g_kfl[row * QKD + tid] = l;
    bsplit(v1 * scale * kv_norm_w[tid + 256], h, l);
    g_kfh[row * QKD + tid + 256] = h; g_kfl[row * QKD + tid + 256] = l;

    if (tid < 32) {
        const float x0 = src[KV_LORA + 2 * tid];
        const float x1 = src[KV_LORA + 2 * tid + 1];
        const float c = fcos[pos * 32 + tid];
        const float s = fsin[pos * 32 + tid];
        bsplit(x0 * c - x1 * s, h, l);
        g_kfh[row * QKD + KV_LORA + 2 * tid] = h;
        g_kfl[row * QKD + KV_LORA + 2 * tid] = l;
        bsplit(x0 * s + x1 * c, h, l);
        g_kfh[row * QKD + KV_LORA + 2 * tid + 1] = h;
        g_kfl[row * QKD + KV_LORA + 2 * tid + 1] = l;
    }
}

// ------------- q rope: split q -> split qf rope cols ------------------------
__global__ void __launch_bounds__(512)
q_process_kernel(const float* __restrict__ fcos, const float* __restrict__ fsin)
{
    const long row = blockIdx.x;
    const int pos = (int)(row & (SEQ - 1));
    const int h = threadIdx.x / 32;
    const int i = threadIdx.x % 32;

    const long si = row * (N_HEADS * QK_HEAD) + h * QK_HEAD + NOPE + 2 * i;
    const float x0 = __bfloat162float(g_qh[si])     + __bfloat162float(g_ql[si]);
    const float x1 = __bfloat162float(g_qh[si + 1]) + __bfloat162float(g_ql[si + 1]);
    const float c = fcos[pos * 32 + i];
    const float s = fsin[pos * 32 + i];
    const long di = row * (N_HEADS * QKD) + h * QKD + KV_LORA + 2 * i;
    bf16 hh, ll;
    bsplit(x0 * c - x1 * s, hh, ll);
    g_qfh[di] = hh; g_qfl[di] = ll;
    bsplit(x0 * s + x1 * c, hh, ll);
    g_qfh[di + 1] = hh; g_qfl[di + 1] = ll;
}

// ------------- softmax: f32 scores + mask -> split P ------------------------
__global__ void __launch_bounds__(256)
softmax_mask_kernel(const float* __restrict__ mask)
{
    const long row = blockIdx.x;
    const int s = (int)(row & (SEQ - 1));
    const float* p = g_sc + row * SEQ;
    const float* mrow = mask + (long)s * SEQ;
    const int tid = threadIdx.x;
    const int t0 = tid * 8;

    float v[8];
    float mx = -INFINITY;
    {
        const float4 a = reinterpret_cast<const float4*>(p + t0)[0];
        const float4 b = reinterpret_cast<const float4*>(p + t0)[1];
        const float4 ma = reinterpret_cast<const float4*>(mrow + t0)[0];
        const float4 mb = reinterpret_cast<const float4*>(mrow + t0)[1];
        v[0] = a.x + ma.x; v[1] = a.y + ma.y; v[2] = a.z + ma.z; v[3] = a.w + ma.w;
        v[4] = b.x + mb.x; v[5] = b.y + mb.y; v[6] = b.z + mb.z; v[7] = b.w + mb.w;
    }
#pragma unroll
    for (int i = 0; i < 8; i++) mx = fmaxf(mx, v[i]);
    __shared__ float red[256];
    red[tid] = mx; __syncthreads();
    for (int o = 128; o > 0; o >>= 1) {
        if (tid < o) red[tid] = fmaxf(red[tid], red[tid + o]);
        __syncthreads();
    }
    mx = red[0]; __syncthreads();

    float sum = 0.f;
#pragma unroll
    for (int i = 0; i < 8; i++) { v[i] = expf(v[i] - mx); sum += v[i]; }
    red[tid] = sum; __syncthreads();
    for (int o = 128; o > 0; o >>= 1) {
        if (tid < o) red[tid] += red[tid + o];
        __syncthreads();
    }
    const float inv = 1.f / red[0];

    __nv_bfloat162 hh[4], ll[4];
#pragma unroll
    for (int i = 0; i < 4; i++) {
        bf16 h0, l0, h1, l1;
        bsplit(v[2 * i] * inv, h0, l0);
        bsplit(v[2 * i + 1] * inv, h1, l1);
        hh[i] = __nv_bfloat162(h0, h1);
        ll[i] = __nv_bfloat162(l0, l1);
    }
#pragma unroll
    for (int i = 0; i < 4; i++) {
        reinterpret_cast<__nv_bfloat162*>(g_Ph + row * SEQ + t0)[i] = hh[i];
        reinterpret_cast<__nv_bfloat162*>(g_Pl + row * SEQ + t0)[i] = ll[i];
    }
}

// ---------------------------------------------------------------------------
extern "C" void kernel_launch(void* const* d_in, const int* in_sizes, int n_in,
                              void* d_out, int out_size)
{
    const float* x         = (const float*)d_in[0];
    const float* fcos      = (const float*)d_in[1];
    const float* fsin      = (const float*)d_in[2];
    const float* mask      = (const float*)d_in[3];
    const float* wq_a      = (const float*)d_in[4];
    const float* q_norm_w  = (const float*)d_in[5];
    const float* wq_b      = (const float*)d_in[6];
    const float* wkv_a     = (const float*)d_in[7];
    const float* kv_norm_w = (const float*)d_in[8];
    const float* wkv_b     = (const float*)d_in[9];
    const float* wo        = (const float*)d_in[10];
    float* out = (float*)d_out;

    bf16 *xh, *xl, *wqah, *wqal, *wqbh, *wqbl, *wkvah, *wkval, *wkvbh, *wkvbl;
    bf16 *woh, *wol, *qah, *qal, *qh, *ql, *kfh, *kfl, *vTh, *vTl, *wTh, *wTl;
    bf16 *qfh, *qfl, *Ph, *Pl, *ath, *atl, *o2h, *o2l;
    float *qaf, *kvf, *sc;
    cudaGetSymbolAddress((void**)&xh, g_xh);     cudaGetSymbolAddress((void**)&xl, g_xl);
    cudaGetSymbolAddress((void**)&wqah, g_wqah); cudaGetSymbolAddress((void**)&wqal, g_wqal);
    cudaGetSymbolAddress((void**)&wqbh, g_wqbh); cudaGetSymbolAddress((void**)&wqbl, g_wqbl);
    cudaGetSymbolAddress((void**)&wkvah, g_wkvah); cudaGetSymbolAddress((void**)&wkval, g_wkval);
    cudaGetSymbolAddress((void**)&wkvbh, g_wkvbh); cudaGetSymbolAddress((void**)&wkvbl, g_wkvbl);
    cudaGetSymbolAddress((void**)&woh, g_woh);   cudaGetSymbolAddress((void**)&wol, g_wol);
    cudaGetSymbolAddress((void**)&qaf, g_qa_f);
    cudaGetSymbolAddress((void**)&qah, g_qah);   cudaGetSymbolAddress((void**)&qal, g_qal);
    cudaGetSymbolAddress((void**)&qh, g_qh);     cudaGetSymbolAddress((void**)&ql, g_ql);
    cudaGetSymbolAddress((void**)&kvf, g_kv_f);
    cudaGetSymbolAddress((void**)&kfh, g_kfh);   cudaGetSymbolAddress((void**)&kfl, g_kfl);
    cudaGetSymbolAddress((void**)&vTh, g_vTh);   cudaGetSymbolAddress((void**)&vTl, g_vTl);
    cudaGetSymbolAddress((void**)&wTh, g_wTh);   cudaGetSymbolAddress((void**)&wTl, g_wTl);
    cudaGetSymbolAddress((void**)&qfh, g_qfh);   cudaGetSymbolAddress((void**)&qfl, g_qfl);
    cudaGetSymbolAddress((void**)&sc, g_sc);
    cudaGetSymbolAddress((void**)&Ph, g_Ph);     cudaGetSymbolAddress((void**)&Pl, g_Pl);
    cudaGetSymbolAddress((void**)&ath, g_ath);   cudaGetSymbolAddress((void**)&atl, g_atl);
    cudaGetSymbolAddress((void**)&o2h, g_o2h);   cudaGetSymbolAddress((void**)&o2l, g_o2l);

    cudaFuncSetAttribute(gemm_bf3<0>, cudaFuncAttributeMaxDynamicSharedMemorySize, SMEM_BYTES);
    cudaFuncSetAttribute(gemm_bf3<1>, cudaFuncAttributeMaxDynamicSharedMemorySize, SMEM_BYTES);

    dim3 blk(256);
    dim3 tb(32, 8);

    // 0. split inputs + weights
    auto splits = [&](const float* s, bf16* h, bf16* l, long n) {
        const long n4 = n / 4;
        int gs = (int)min((n4 + 255) / 256, (long)4096);
        split_kernel<<<gs, blk>>>(s, h, l, n4);
    };
    splits(x,     xh,    xl,    (long)ROWS * DIM);
    splits(wq_a,  wqah,  wqal,  (long)Q_LORA * DIM);
    splits(wq_b,  wqbh,  wqbl,  (long)N_HEADS * QK_HEAD * Q_LORA);
    splits(wkv_a, wkvah, wkval, (long)QKD * DIM);
    splits(wkv_b, wkvbh, wkvbl, (long)N_HEADS * 256 * KV_LORA);
    splits(wo,    woh,   wol,   (long)DIM * DIM);

    // 1. qa_f = x @ wq_a^T  [4096,1536] K=2048 (f32 out)
    gemm_bf3<0><<<dim3(ROWS/128, Q_LORA/128, 1), blk, SMEM_BYTES>>>(
        xh, xl, wqah, wqal, qaf, nullptr, nullptr,
        ROWS, Q_LORA, DIM, DIM, DIM, Q_LORA, 0,0, 0,0, 0,0, 1, 1.f);

    // 2. rmsnorm -> split qa
    rmsnorm_qa_kernel<<<ROWS, blk>>>(q_norm_w);

    // 3. q = qa @ wq_b^T  [4096,3072] K=1536 (split out)
    gemm_bf3<1><<<dim3(ROWS/128, (N_HEADS*QK_HEAD)/128, 1), blk, SMEM_BYTES>>>(
        qah, qal, wqbh, wqbl, nullptr, qh, ql,
        ROWS, N_HEADS*QK_HEAD, Q_LORA, Q_LORA, Q_LORA, N_HEADS*QK_HEAD,
        0,0, 0,0, 0,0, 1, 1.f);

    // 4. kv_f = x @ wkv_a^T  [4096,576] K=2048 (f32 out)
    gemm_bf3<0><<<dim3(ROWS/128, (QKD+127)/128, 1), blk, SMEM_BYTES>>>(
        xh, xl, wkvah, wkval, kvf, nullptr, nullptr,
        ROWS, QKD, DIM, DIM, DIM, QKD, 0,0, 0,0, 0,0, 1, 1.f);

    // 5. kv -> split kf (rmsnorm + rope)
    kv_process_kernel<<<ROWS, blk>>>(kv_norm_w, fcos, fsin);

    // 6. rope(q_pe) -> split qf rope cols
    q_process_kernel<<<ROWS, 512>>>(fcos, fsin);

    // 6b. vT[b][c][t] = kf[b*2048+t][c]
    transpose_bf2<<<dim3(SEQ/32, KV_LORA/32, BATCH), tb>>>(
        kfh, kfl, vTh, vTl, QKD, SEQ, (long)SEQ*QKD, (long)KV_LORA*SEQ);
    // 6c. wT[h][c][d] = wkvb[h*256+d][c] (nope rows)
    transpose_bf2<<<dim3(NOPE/32, KV_LORA/32, N_HEADS), tb>>>(
        wkvbh, wkvbl, wTh, wTl, KV_LORA, NOPE, (long)256*KV_LORA, (long)KV_LORA*NOPE);

    // 7. qf[:,:,0:512] = q_nope @ wT[h]^T  (batched h) K=128 (split out)
    gemm_bf3<1><<<dim3(ROWS/128, KV_LORA/128, N_HEADS), blk, SMEM_BYTES>>>(
        qh, ql, wTh, wTl, nullptr, qfh, qfl,
        ROWS, KV_LORA, NOPE, N_HEADS*QK_HEAD, NOPE, N_HEADS*QKD,
        0, QK_HEAD, 0, (long)KV_LORA*NOPE, 0, QKD, N_HEADS, 1.f);

    // 8. scores = SCALE * qf @ kf^T  (batched b,h) K=576 (f32 out)
    gemm_bf3<0><<<dim3(SEQ/128, SEQ/128, BATCH*N_HEADS), blk, SMEM_BYTES>>>(
        qfh, qfl, kfh, kfl, sc, nullptr, nullptr,
        SEQ, SEQ, QKD, N_HEADS*QKD, QKD, SEQ,
        (long)SEQ*N_HEADS*QKD, QKD,
        (long)SEQ*QKD, 0,
        (long)N_HEADS*SEQ*SEQ, (long)SEQ*SEQ,
        N_HEADS, SCALE_F);

    // 9. softmax -> split P
    softmax_mask_kernel<<<BATCH*N_HEADS*SEQ, blk>>>(mask);

    // 10. attno = P @ vT^T  (batched b,h) K=2048 (split out)
    gemm_bf3<1><<<dim3(SEQ/128, KV_LORA/128, BATCH*N_HEADS), blk, SMEM_BYTES>>>(
        Ph, Pl, vTh, vTl, nullptr, ath, atl,
        SEQ, KV_LORA, SEQ, SEQ, SEQ, N_HEADS*KV_LORA,
        (long)N_HEADS*SEQ*SEQ, (long)SEQ*SEQ,
        (long)KV_LORA*SEQ, 0,
        (long)SEQ*N_HEADS*KV_LORA, KV_LORA,
        N_HEADS, 1.f);

    // 11. o2 = attno @ wkvb_v^T  (batched h) K=512 (split out)
    gemm_bf3<1><<<dim3(ROWS/128, V_HEAD/128, N_HEADS), blk, SMEM_BYTES>>>(
        ath, atl, wkvbh + (size_t)NOPE*KV_LORA, wkvbl + (size_t)NOPE*KV_LORA,
        nullptr, o2h, o2l,
        ROWS, V_HEAD, KV_LORA, N_HEADS*KV_LORA, KV_LORA, DIM,
        0, KV_LORA, 0, (long)256*KV_LORA, 0, V_HEAD, N_HEADS, 1.f);

    // 12. out = o2 @ wo^T  [4096,2048] K=2048 (f32 out)
    gemm_bf3<0><<<dim3(ROWS/128, DIM/128, 1), blk, SMEM_BYTES>>>(
        o2h, o2l, woh, wol, out, nullptr, nullptr,
        ROWS, DIM, DIM, DIM, DIM, DIM, 0,0, 0,0, 0,0, 1, 1.f);
}

// round 6
// speedup vs baseline: 4.7997x; 1.3800x over previous
#include <cuda_runtime.h>
#include <cuda_bf16.h>
#include <math.h>
#include <stdint.h>

// ---------------------------------------------------------------------------
// MLA forward. Split-bf16 3-term tensor-core GEMMs (Ah.Bh + Ah.Bl + Al.Bh).
// Round 6: causal block skipping -- scores GEMM computes only lower-triangular
// tiles, P.V GEMM bounds its K loop at the diagonal (P upper triangle is
// EXACTLY zero after masked softmax), softmax rows only touch computed tiles.
// PTX-stable on compute_103 (no tcgen05).
// ---------------------------------------------------------------------------

#define DIM     2048
#define N_HEADS 16
#define Q_LORA  1536
#define KV_LORA 512
#define NOPE    128
#define ROPE    64
#define V_HEAD  128
#define QK_HEAD 192
#define BATCH   2
#define SEQ     2048
#define ROWS    (BATCH * SEQ)
#define QKD     (KV_LORA + ROPE)        // 576
#define SCALE_F 0.0721687836487032f
#define EPS_F   1e-6f

typedef __nv_bfloat16 bf16;

// ------------------------- scratch (device globals) -------------------------
__device__ __align__(256) bf16  g_xh   [(size_t)ROWS * DIM];
__device__ __align__(256) bf16  g_xl   [(size_t)ROWS * DIM];
__device__ __align__(256) bf16  g_wqah [(size_t)Q_LORA * DIM];
__device__ __align__(256) bf16  g_wqal [(size_t)Q_LORA * DIM];
__device__ __align__(256) bf16  g_wqbh [(size_t)N_HEADS * QK_HEAD * Q_LORA];
__device__ __align__(256) bf16  g_wqbl [(size_t)N_HEADS * QK_HEAD * Q_LORA];
__device__ __align__(256) bf16  g_wkvah[(size_t)QKD * DIM];
__device__ __align__(256) bf16  g_wkval[(size_t)QKD * DIM];
__device__ __align__(256) bf16  g_wkvbh[(size_t)N_HEADS * 256 * KV_LORA];
__device__ __align__(256) bf16  g_wkvbl[(size_t)N_HEADS * 256 * KV_LORA];
__device__ __align__(256) bf16  g_woh  [(size_t)DIM * DIM];
__device__ __align__(256) bf16  g_wol  [(size_t)DIM * DIM];

__device__ __align__(256) float g_qa_f [(size_t)ROWS * Q_LORA];
__device__ __align__(256) bf16  g_qah  [(size_t)ROWS * Q_LORA];
__device__ __align__(256) bf16  g_qal  [(size_t)ROWS * Q_LORA];
__device__ __align__(256) bf16  g_qh   [(size_t)ROWS * N_HEADS * QK_HEAD];
__device__ __align__(256) bf16  g_ql   [(size_t)ROWS * N_HEADS * QK_HEAD];
__device__ __align__(256) float g_kv_f [(size_t)ROWS * QKD];
__device__ __align__(256) bf16  g_kfh  [(size_t)ROWS * QKD];
__device__ __align__(256) bf16  g_kfl  [(size_t)ROWS * QKD];
__device__ __align__(256) bf16  g_vTh  [(size_t)BATCH * KV_LORA * SEQ];
__device__ __align__(256) bf16  g_vTl  [(size_t)BATCH * KV_LORA * SEQ];
__device__ __align__(256) bf16  g_wTh  [(size_t)N_HEADS * KV_LORA * NOPE];
__device__ __align__(256) bf16  g_wTl  [(size_t)N_HEADS * KV_LORA * NOPE];
__device__ __align__(256) bf16  g_qfh  [(size_t)ROWS * N_HEADS * QKD];
__device__ __align__(256) bf16  g_qfl  [(size_t)ROWS * N_HEADS * QKD];
__device__ __align__(256) float g_sc   [(size_t)BATCH * N_HEADS * SEQ * SEQ];
__device__ __align__(256) bf16  g_Ph   [(size_t)BATCH * N_HEADS * SEQ * SEQ];
__device__ __align__(256) bf16  g_Pl   [(size_t)BATCH * N_HEADS * SEQ * SEQ];
__device__ __align__(256) bf16  g_ath  [(size_t)ROWS * N_HEADS * KV_LORA];
__device__ __align__(256) bf16  g_atl  [(size_t)ROWS * N_HEADS * KV_LORA];
__device__ __align__(256) bf16  g_o2h  [(size_t)ROWS * DIM];
__device__ __align__(256) bf16  g_o2l  [(size_t)ROWS * DIM];

// ----------------------------- helpers --------------------------------------
__device__ __forceinline__ uint32_t smem_u32(const void* p) {
    uint32_t a;
    asm("{ .reg .u64 t; cvta.to.shared.u64 t, %1; cvt.u32.u64 %0, t; }"
        : "=r"(a) : "l"(p));
    return a;
}
__device__ __forceinline__ void cp16(uint32_t dst, const void* src) {
    asm volatile("cp.async.ca.shared.global [%0], [%1], 16;"
                 :: "r"(dst), "l"(src) : "memory");
}
#define CP_COMMIT() asm volatile("cp.async.commit_group;" ::: "memory")
#define CP_WAIT(n)  asm volatile("cp.async.wait_group %0;" :: "n"(n) : "memory")

__device__ __forceinline__ void ldm_x4(uint32_t* r, uint32_t addr) {
    asm volatile("ldmatrix.sync.aligned.m8n8.x4.shared.b16 {%0,%1,%2,%3}, [%4];"
                 : "=r"(r[0]), "=r"(r[1]), "=r"(r[2]), "=r"(r[3]) : "r"(addr));
}
__device__ __forceinline__ void mma_bf16(float* d, const uint32_t* a,
                                         const uint32_t* b) {
    asm volatile(
        "mma.sync.aligned.m16n8k16.row.col.f32.bf16.bf16.f32 "
        "{%0,%1,%2,%3}, {%4,%5,%6,%7}, {%8,%9}, {%0,%1,%2,%3};"
        : "+f"(d[0]), "+f"(d[1]), "+f"(d[2]), "+f"(d[3])
        : "r"(a[0]), "r"(a[1]), "r"(a[2]), "r"(a[3]), "r"(b[0]), "r"(b[1]));
}
__device__ __forceinline__ void bsplit(float x, bf16& h, bf16& l) {
    h = __float2bfloat16_rn(x);
    l = __float2bfloat16_rn(x - __bfloat162float(h));
}

// ----------------------- GEMM: C = alpha * A.B^T ----------------------------
// A,B pre-split bf16 hi/lo, K-major. M%128==0, K%32==0, N arbitrary.
// OUTM=0: C f32.  OUTM=1: C split to Ch/Cl bf16.
// mode bit0: skip tiles with n0 > m0 (causal scores)
// mode bit1: limit K to m0+128     (causal P.V)
#define ROWB 80
#define TILE_BYTES (128 * ROWB)
#define STAGE_BYTES (4 * TILE_BYTES)
#define SMEM_BYTES (2 * STAGE_BYTES)   // 81920

__device__ __forceinline__ void load_tile_bf(uint32_t dst, const bf16* __restrict__ src,
                                             int ld, int k0, int limit, int tid) {
#pragma unroll
    for (int it = 0; it < 2; it++) {
        const int idx = tid + it * 256;
        const int row = idx >> 2, seg = idx & 3;
        const uint32_t d = dst + (uint32_t)(row * ROWB + seg * 16);
        if (row < limit) {
            cp16(d, src + (size_t)row * ld + k0 + seg * 8);
        } else {
            asm volatile("st.shared.v4.b32 [%0], {%1,%1,%1,%1};"
                         :: "r"(d), "r"(0) : "memory");
        }
    }
}

template <int OUTM>
__global__ void __launch_bounds__(256)
gemm_bf3(const bf16* __restrict__ Ah, const bf16* __restrict__ Al,
         const bf16* __restrict__ Bh, const bf16* __restrict__ Bl,
         float* __restrict__ C, bf16* __restrict__ Ch, bf16* __restrict__ Cl,
         int M, int N, int K, int lda, int ldb, int ldc,
         long sAo, long sAi, long sBo, long sBi, long sCo, long sCi,
         int inner, float alpha, int mode)
{
    const int m0 = blockIdx.x * 128, n0 = blockIdx.y * 128;
    if ((mode & 1) && n0 > m0) return;          // causal tile skip

    extern __shared__ char smem[];
    const uint32_t sb = smem_u32(smem);
    const int tid = threadIdx.x, lane = tid & 31, wid = tid >> 5;
    const int wm = wid & 1, wn = wid >> 1;
    const int g = lane >> 2, tig = lane & 3;

    const int z = blockIdx.z, zo = z / inner, zi = z - zo * inner;
    const long ofAB = (long)zo * sAo + (long)zi * sAi;
    const long ofB  = (long)zo * sBo + (long)zi * sBi;
    const long ofC  = (long)zo * sCo + (long)zi * sCi;
    Ah += ofAB; Al += ofAB;
    Bh += ofB;  Bl += ofB;

    const bf16* Ath = Ah + (size_t)m0 * lda;
    const bf16* Atl = Al + (size_t)m0 * lda;
    const bf16* Bth = Bh + (size_t)n0 * ldb;
    const bf16* Btl = Bl + (size_t)n0 * ldb;
    const int nlim = min(128, N - n0);

    float acc[4][4][4];
#pragma unroll
    for (int i = 0; i < 4; i++)
#pragma unroll
        for (int j = 0; j < 4; j++)
#pragma unroll
            for (int r = 0; r < 4; r++) acc[i][j][r] = 0.f;

    const int Keff = (mode & 2) ? min(K, m0 + 128) : K;   // causal K bound
    const int nch = Keff >> 5;

    load_tile_bf(sb + 0 * TILE_BYTES, Ath, lda, 0, 128, tid);
    load_tile_bf(sb + 1 * TILE_BYTES, Atl, lda, 0, 128, tid);
    load_tile_bf(sb + 2 * TILE_BYTES, Bth, ldb, 0, nlim, tid);
    load_tile_bf(sb + 3 * TILE_BYTES, Btl, ldb, 0, nlim, tid);
    CP_COMMIT();

    const uint32_t aoffL = (uint32_t)((wm * 64 + (lane & 15)) * ROWB + (lane >> 4) * 16);
    const uint32_t boffL = (uint32_t)((wn * 32 + ((lane >> 4) & 1) * 8 + (lane & 7)) * ROWB
                                      + ((lane >> 3) & 1) * 16);

    for (int c = 0; c < nch; c++) {
        if (c + 1 < nch) {
            const uint32_t nb = sb + ((c + 1) & 1) * STAGE_BYTES;
            load_tile_bf(nb + 0 * TILE_BYTES, Ath, lda, (c + 1) << 5, 128, tid);
            load_tile_bf(nb + 1 * TILE_BYTES, Atl, lda, (c + 1) << 5, 128, tid);
            load_tile_bf(nb + 2 * TILE_BYTES, Bth, ldb, (c + 1) << 5, nlim, tid);
            load_tile_bf(nb + 3 * TILE_BYTES, Btl, ldb, (c + 1) << 5, nlim, tid);
            CP_COMMIT();
            CP_WAIT(1);
        } else {
            CP_WAIT(0);
        }
        __syncthreads();

        const uint32_t base = sb + (c & 1) * STAGE_BYTES;
        const uint32_t aA = base + aoffL;
        const uint32_t bA = base + 2 * TILE_BYTES + boffL;

#pragma unroll
        for (int ks = 0; ks < 2; ks++) {
            uint32_t ah[4][4], al[4][4], bh[2][4], bl[2][4];
#pragma unroll
            for (int i = 0; i < 4; i++) {
                ldm_x4(ah[i], aA + ks * 32 + i * 16 * ROWB);
                ldm_x4(al[i], aA + TILE_BYTES + ks * 32 + i * 16 * ROWB);
            }
#pragma unroll
            for (int jj = 0; jj < 2; jj++) {
                ldm_x4(bh[jj], bA + ks * 32 + jj * 16 * ROWB);
                ldm_x4(bl[jj], bA + TILE_BYTES + ks * 32 + jj * 16 * ROWB);
            }
#pragma unroll
            for (int i = 0; i < 4; i++)
#pragma unroll
                for (int j = 0; j < 4; j++) {
                    const uint32_t* bhp = &bh[j >> 1][(j & 1) * 2];
                    const uint32_t* blp = &bl[j >> 1][(j & 1) * 2];
                    mma_bf16(acc[i][j], al[i], bhp);
                    mma_bf16(acc[i][j], ah[i], blp);
                    mma_bf16(acc[i][j], ah[i], bhp);
                }
        }
        __syncthreads();
    }

    // epilogue
#pragma unroll
    for (int i = 0; i < 4; i++) {
        const int r0 = m0 + wm * 64 + i * 16 + g;
#pragma unroll
        for (int j = 0; j < 4; j++) {
            const int col = n0 + wn * 32 + j * 8 + tig * 2;
            if (col >= N) continue;
            const float c0 = alpha * acc[i][j][0], c1 = alpha * acc[i][j][1];
            const float c2 = alpha * acc[i][j][2], c3 = alpha * acc[i][j][3];
            if (OUTM == 0) {
                float* p0 = C + ofC + (size_t)r0 * ldc + col;
                float* p1 = C + ofC + (size_t)(r0 + 8) * ldc + col;
                if (col + 1 < N) {
                    *reinterpret_cast<float2*>(p0) = make_float2(c0, c1);
                    *reinterpret_cast<float2*>(p1) = make_float2(c2, c3);
                } else { p0[0] = c0; p1[0] = c2; }
            } else {
                bf16 h0, l0, h1, l1, h2, l2, h3, l3;
                bsplit(c0, h0, l0); bsplit(c1, h1, l1);
                bsplit(c2, h2, l2); bsplit(c3, h3, l3);
                *reinterpret_cast<__nv_bfloat162*>(Ch + ofC + (size_t)r0 * ldc + col)
                    = __nv_bfloat162(h0, h1);
                *reinterpret_cast<__nv_bfloat162*>(Cl + ofC + (size_t)r0 * ldc + col)
                    = __nv_bfloat162(l0, l1);
                *reinterpret_cast<__nv_bfloat162*>(Ch + ofC + (size_t)(r0 + 8) * ldc + col)
                    = __nv_bfloat162(h2, h3);
                *reinterpret_cast<__nv_bfloat162*>(Cl + ofC + (size_t)(r0 + 8) * ldc + col)
                    = __nv_bfloat162(l2, l3);
            }
        }
    }
}

// ---------------------- elementwise split f32 -> bf16 hi/lo ------------------
__global__ void __launch_bounds__(256)
split_kernel(const float* __restrict__ src, bf16* __restrict__ h,
             bf16* __restrict__ l, long n4)
{
    const long stride = (long)gridDim.x * blockDim.x;
    for (long i = blockIdx.x * (long)blockDim.x + threadIdx.x; i < n4; i += stride) {
        const float4 v = reinterpret_cast<const float4*>(src)[i];
        bf16 h0, l0, h1, l1, h2, l2, h3, l3;
        bsplit(v.x, h0, l0); bsplit(v.y, h1, l1);
        bsplit(v.z, h2, l2); bsplit(v.w, h3, l3);
        reinterpret_cast<__nv_bfloat162*>(h)[i * 2]     = __nv_bfloat162(h0, h1);
        reinterpret_cast<__nv_bfloat162*>(h)[i * 2 + 1] = __nv_bfloat162(h2, h3);
        reinterpret_cast<__nv_bfloat162*>(l)[i * 2]     = __nv_bfloat162(l0, l1);
        reinterpret_cast<__nv_bfloat162*>(l)[i * 2 + 1] = __nv_bfloat162(l2, l3);
    }
}

// ------------------- dual bf16 transpose (32x32 tiles) ----------------------
__global__ void __launch_bounds__(256)
transpose_bf2(const bf16* __restrict__ sh, const bf16* __restrict__ sl,
              bf16* __restrict__ dh, bf16* __restrict__ dl,
              int lds, int ldd, long sS, long sD)
{
    __shared__ float th[32][33], tl[32][33];
    const int z = blockIdx.z;
    sh += (long)z * sS; sl += (long)z * sS;
    dh += (long)z * sD; dl += (long)z * sD;
    const int r0 = blockIdx.x * 32, c0 = blockIdx.y * 32;
    const int tx = threadIdx.x, ty = threadIdx.y;
#pragma unroll
    for (int i = 0; i < 4; i++) {
        const long s = (long)(r0 + ty + 8 * i) * lds + c0 + tx;
        th[ty + 8 * i][tx] = __bfloat162float(sh[s]);
        tl[ty + 8 * i][tx] = __bfloat162float(sl[s]);
    }
    __syncthreads();
#pragma unroll
    for (int i = 0; i < 4; i++) {
        const long d = (long)(c0 + ty + 8 * i) * ldd + r0 + tx;
        dh[d] = __float2bfloat16_rn(th[tx][ty + 8 * i]);
        dl[d] = __float2bfloat16_rn(tl[tx][ty + 8 * i]);
    }
}

// --------------------------- rmsnorm: f32 -> split --------------------------
__global__ void __launch_bounds__(256)
rmsnorm_qa_kernel(const float* __restrict__ w)
{
    const long row = blockIdx.x;
    const float* p = g_qa_f + row * Q_LORA;
    const int tid = threadIdx.x;
    float v[6];
    float ss = 0.f;
#pragma unroll
    for (int i = 0; i < 6; i++) { v[i] = p[tid + i * 256]; ss += v[i] * v[i]; }
    __shared__ float red[256];
    red[tid] = ss; __syncthreads();
    for (int o = 128; o > 0; o >>= 1) {
        if (tid < o) red[tid] += red[tid + o];
        __syncthreads();
    }
    const float scale = rsqrtf(red[0] / (float)Q_LORA + EPS_F);
#pragma unroll
    for (int i = 0; i < 6; i++) {
        const int c = tid + i * 256;
        bf16 h, l;
        bsplit(v[i] * scale * w[c], h, l);
        g_qah[row * Q_LORA + c] = h;
        g_qal[row * Q_LORA + c] = l;
    }
}

// ------------- kv_process: f32 kv -> split kf (norm + rope) -----------------
__global__ void __launch_bounds__(256)
kv_process_kernel(const float* __restrict__ kv_norm_w,
                  const float* __restrict__ fcos,
                  const float* __restrict__ fsin)
{
    const long row = blockIdx.x;
    const int pos = (int)(row & (SEQ - 1));
    const float* src = g_kv_f + row * QKD;
    const int tid = threadIdx.x;

    const float v0 = src[tid], v1 = src[tid + 256];
    __shared__ float red[256];
    red[tid] = v0 * v0 + v1 * v1; __syncthreads();
    for (int o = 128; o > 0; o >>= 1) {
        if (tid < o) red[tid] += red[tid + o];
        __syncthreads();
    }
    const float scale = rsqrtf(red[0] / (float)KV_LORA + EPS_F);
    bf16 h, l;
    bsplit(v0 * scale * kv_norm_w[tid], h, l);
    g_kfh[row * QKD + tid] = h; g_kfl[row * QKD + tid] = l;
    bsplit(v1 * scale * kv_norm_w[tid + 256], h, l);
    g_kfh[row * QKD + tid + 256] = h; g_kfl[row * QKD + tid + 256] = l;

    if (tid < 32) {
        const float x0 = src[KV_LORA + 2 * tid];
        const float x1 = src[KV_LORA + 2 * tid + 1];
        const float c = fcos[pos * 32 + tid];
        const float s = fsin[pos * 32 + tid];
        bsplit(x0 * c - x1 * s, h, l);
        g_kfh[row * QKD + KV_LORA + 2 * tid] = h;
        g_kfl[row * QKD + KV_LORA + 2 * tid] = l;
        bsplit(x0 * s + x1 * c, h, l);
        g_kfh[row * QKD + KV_LORA + 2 * tid + 1] = h;
        g_kfl[row * QKD + KV_LORA + 2 * tid + 1] = l;
    }
}

// ------------- q rope -------------------------------------------------------
__global__ void __launch_bounds__(512)
q_process_kernel(const float* __restrict__ fcos, const float* __restrict__ fsin)
{
    const long row = blockIdx.x;
    const int pos = (int)(row & (SEQ - 1));
    const int h = threadIdx.x / 32;
    const int i = threadIdx.x % 32;

    const long si = row * (N_HEADS * QK_HEAD) + h * QK_HEAD + NOPE + 2 * i;
    const float x0 = __bfloat162float(g_qh[si])     + __bfloat162float(g_ql[si]);
    const float x1 = __bfloat162float(g_qh[si + 1]) + __bfloat162float(g_ql[si + 1]);
    const float c = fcos[pos * 32 + i];
    const float s = fsin[pos * 32 + i];
    const long di = row * (N_HEADS * QKD) + h * QKD + KV_LORA + 2 * i;
    bf16 hh, ll;
    bsplit(x0 * c - x1 * s, hh, ll);
    g_qfh[di] = hh; g_qfl[di] = ll;
    bsplit(x0 * s + x1 * c, hh, ll);
    g_qfh[di + 1] = hh; g_qfl[di + 1] = ll;
}

// ------------- softmax (causal extent only) ---------------------------------
// Row s reads/writes only t < T = tile-aligned bound; masked entries in
// [s+1, T) underflow to exactly 0 after exp.
__global__ void __launch_bounds__(256)
softmax_mask_kernel(const float* __restrict__ mask)
{
    const long row = blockIdx.x;
    const int s = (int)(row & (SEQ - 1));
    const int T = ((s >> 7) + 1) << 7;          // 128..2048, tile aligned
    const float* p = g_sc + row * SEQ;
    const float* mrow = mask + (long)s * SEQ;
    const int tid = threadIdx.x;
    const int t0 = tid * 8;
    const bool act = t0 < T;

    float v[8];
    float mx = -INFINITY;
    if (act) {
        const float4 a = reinterpret_cast<const float4*>(p + t0)[0];
        const float4 b = reinterpret_cast<const float4*>(p + t0)[1];
        const float4 ma = reinterpret_cast<const float4*>(mrow + t0)[0];
        const float4 mb = reinterpret_cast<const float4*>(mrow + t0)[1];
        v[0] = a.x + ma.x; v[1] = a.y + ma.y; v[2] = a.z + ma.z; v[3] = a.w + ma.w;
        v[4] = b.x + mb.x; v[5] = b.y + mb.y; v[6] = b.z + mb.z; v[7] = b.w + mb.w;
#pragma unroll
        for (int i = 0; i < 8; i++) mx = fmaxf(mx, v[i]);
    }
    __shared__ float red[256];
    red[tid] = mx; __syncthreads();
    for (int o = 128; o > 0; o >>= 1) {
        if (tid < o) red[tid] = fmaxf(red[tid], red[tid + o]);
        __syncthreads();
    }
    mx = red[0]; __syncthreads();

    float sum = 0.f;
    if (act) {
#pragma unroll
        for (int i = 0; i < 8; i++) { v[i] = expf(v[i] - mx); sum += v[i]; }
    }
    red[tid] = sum; __syncthreads();
    for (int o = 128; o > 0; o >>= 1) {
        if (tid < o) red[tid] += red[tid + o];
        __syncthreads();
    }
    const float inv = 1.f / red[0];

    if (act) {
#pragma unroll
        for (int i = 0; i < 4; i++) {
            bf16 h0, l0, h1, l1;
            bsplit(v[2 * i] * inv, h0, l0);
            bsplit(v[2 * i + 1] * inv, h1, l1);
            reinterpret_cast<__nv_bfloat162*>(g_Ph + row * SEQ + t0)[i]
                = __nv_bfloat162(h0, h1);
            reinterpret_cast<__nv_bfloat162*>(g_Pl + row * SEQ + t0)[i]
                = __nv_bfloat162(l0, l1);
        }
    }
}

// ---------------------------------------------------------------------------
extern "C" void kernel_launch(void* const* d_in, const int* in_sizes, int n_in,
                              void* d_out, int out_size)
{
    const float* x         = (const float*)d_in[0];
    const float* fcos      = (const float*)d_in[1];
    const float* fsin      = (const float*)d_in[2];
    const float* mask      = (const float*)d_in[3];
    const float* wq_a      = (const float*)d_in[4];
    const float* q_norm_w  = (const float*)d_in[5];
    const float* wq_b      = (const float*)d_in[6];
    const float* wkv_a     = (const float*)d_in[7];
    const float* kv_norm_w = (const float*)d_in[8];
    const float* wkv_b     = (const float*)d_in[9];
    const float* wo        = (const float*)d_in[10];
    float* out = (float*)d_out;

    bf16 *xh, *xl, *wqah, *wqal, *wqbh, *wqbl, *wkvah, *wkval, *wkvbh, *wkvbl;
    bf16 *woh, *wol, *qah, *qal, *qh, *ql, *kfh, *kfl, *vTh, *vTl, *wTh, *wTl;
    bf16 *qfh, *qfl, *Ph, *Pl, *ath, *atl, *o2h, *o2l;
    float *qaf, *kvf, *sc;
    cudaGetSymbolAddress((void**)&xh, g_xh);     cudaGetSymbolAddress((void**)&xl, g_xl);
    cudaGetSymbolAddress((void**)&wqah, g_wqah); cudaGetSymbolAddress((void**)&wqal, g_wqal);
    cudaGetSymbolAddress((void**)&wqbh, g_wqbh); cudaGetSymbolAddress((void**)&wqbl, g_wqbl);
    cudaGetSymbolAddress((void**)&wkvah, g_wkvah); cudaGetSymbolAddress((void**)&wkval, g_wkval);
    cudaGetSymbolAddress((void**)&wkvbh, g_wkvbh); cudaGetSymbolAddress((void**)&wkvbl, g_wkvbl);
    cudaGetSymbolAddress((void**)&woh, g_woh);   cudaGetSymbolAddress((void**)&wol, g_wol);
    cudaGetSymbolAddress((void**)&qaf, g_qa_f);
    cudaGetSymbolAddress((void**)&qah, g_qah);   cudaGetSymbolAddress((void**)&qal, g_qal);
    cudaGetSymbolAddress((void**)&qh, g_qh);     cudaGetSymbolAddress((void**)&ql, g_ql);
    cudaGetSymbolAddress((void**)&kvf, g_kv_f);
    cudaGetSymbolAddress((void**)&kfh, g_kfh);   cudaGetSymbolAddress((void**)&kfl, g_kfl);
    cudaGetSymbolAddress((void**)&vTh, g_vTh);   cudaGetSymbolAddress((void**)&vTl, g_vTl);
    cudaGetSymbolAddress((void**)&wTh, g_wTh);   cudaGetSymbolAddress((void**)&wTl, g_wTl);
    cudaGetSymbolAddress((void**)&qfh, g_qfh);   cudaGetSymbolAddress((void**)&qfl, g_qfl);
    cudaGetSymbolAddress((void**)&sc, g_sc);
    cudaGetSymbolAddress((void**)&Ph, g_Ph);     cudaGetSymbolAddress((void**)&Pl, g_Pl);
    cudaGetSymbolAddress((void**)&ath, g_ath);   cudaGetSymbolAddress((void**)&atl, g_atl);
    cudaGetSymbolAddress((void**)&o2h, g_o2h);   cudaGetSymbolAddress((void**)&o2l, g_o2l);

    cudaFuncSetAttribute(gemm_bf3<0>, cudaFuncAttributeMaxDynamicSharedMemorySize, SMEM_BYTES);
    cudaFuncSetAttribute(gemm_bf3<1>, cudaFuncAttributeMaxDynamicSharedMemorySize, SMEM_BYTES);

    dim3 blk(256);
    dim3 tb(32, 8);

    // 0. split inputs + weights
    auto splits = [&](const float* s, bf16* h, bf16* l, long n) {
        const long n4 = n / 4;
        int gs = (int)min((n4 + 255) / 256, (long)4096);
        split_kernel<<<gs, blk>>>(s, h, l, n4);
    };
    splits(x,     xh,    xl,    (long)ROWS * DIM);
    splits(wq_a,  wqah,  wqal,  (long)Q_LORA * DIM);
    splits(wq_b,  wqbh,  wqbl,  (long)N_HEADS * QK_HEAD * Q_LORA);
    splits(wkv_a, wkvah, wkval, (long)QKD * DIM);
    splits(wkv_b, wkvbh, wkvbl, (long)N_HEADS * 256 * KV_LORA);
    splits(wo,    woh,   wol,   (long)DIM * DIM);

    // 1. qa_f = x @ wq_a^T  (f32 out)
    gemm_bf3<0><<<dim3(ROWS/128, Q_LORA/128, 1), blk, SMEM_BYTES>>>(
        xh, xl, wqah, wqal, qaf, nullptr, nullptr,
        ROWS, Q_LORA, DIM, DIM, DIM, Q_LORA, 0,0, 0,0, 0,0, 1, 1.f, 0);

    // 2. rmsnorm -> split qa
    rmsnorm_qa_kernel<<<ROWS, blk>>>(q_norm_w);

    // 3. q = qa @ wq_b^T  (split out)
    gemm_bf3<1><<<dim3(ROWS/128, (N_HEADS*QK_HEAD)/128, 1), blk, SMEM_BYTES>>>(
        qah, qal, wqbh, wqbl, nullptr, qh, ql,
        ROWS, N_HEADS*QK_HEAD, Q_LORA, Q_LORA, Q_LORA, N_HEADS*QK_HEAD,
        0,0, 0,0, 0,0, 1, 1.f, 0);

    // 4. kv_f = x @ wkv_a^T  (f32 out)
    gemm_bf3<0><<<dim3(ROWS/128, (QKD+127)/128, 1), blk, SMEM_BYTES>>>(
        xh, xl, wkvah, wkval, kvf, nullptr, nullptr,
        ROWS, QKD, DIM, DIM, DIM, QKD, 0,0, 0,0, 0,0, 1, 1.f, 0);

    // 5. kv -> split kf
    kv_process_kernel<<<ROWS, blk>>>(kv_norm_w, fcos, fsin);

    // 6. rope(q_pe) -> qf
    q_process_kernel<<<ROWS, 512>>>(fcos, fsin);

    // 6b/6c. transposes
    transpose_bf2<<<dim3(SEQ/32, KV_LORA/32, BATCH), tb>>>(
        kfh, kfl, vTh, vTl, QKD, SEQ, (long)SEQ*QKD, (long)KV_LORA*SEQ);
    transpose_bf2<<<dim3(NOPE/32, KV_LORA/32, N_HEADS), tb>>>(
        wkvbh, wkvbl, wTh, wTl, KV_LORA, NOPE, (long)256*KV_LORA, (long)KV_LORA*NOPE);

    // 7. qf[:,:,0:512] = q_nope @ wT[h]^T  (batched h)
    gemm_bf3<1><<<dim3(ROWS/128, KV_LORA/128, N_HEADS), blk, SMEM_BYTES>>>(
        qh, ql, wTh, wTl, nullptr, qfh, qfl,
        ROWS, KV_LORA, NOPE, N_HEADS*QK_HEAD, NOPE, N_HEADS*QKD,
        0, QK_HEAD, 0, (long)KV_LORA*NOPE, 0, QKD, N_HEADS, 1.f, 0);

    // 8. scores = SCALE * qf @ kf^T  (causal tiles only)
    gemm_bf3<0><<<dim3(SEQ/128, SEQ/128, BATCH*N_HEADS), blk, SMEM_BYTES>>>(
        qfh, qfl, kfh, kfl, sc, nullptr, nullptr,
        SEQ, SEQ, QKD, N_HEADS*QKD, QKD, SEQ,
        (long)SEQ*N_HEADS*QKD, QKD,
        (long)SEQ*QKD, 0,
        (long)N_HEADS*SEQ*SEQ, (long)SEQ*SEQ,
        N_HEADS, SCALE_F, 1);

    // 9. softmax -> split P (causal extent)
    softmax_mask_kernel<<<BATCH*N_HEADS*SEQ, blk>>>(mask);

    // 10. attno = P @ vT^T  (causal K bound)
    gemm_bf3<1><<<dim3(SEQ/128, KV_LORA/128, BATCH*N_HEADS), blk, SMEM_BYTES>>>(
        Ph, Pl, vTh, vTl, nullptr, ath, atl,
        SEQ, KV_LORA, SEQ, SEQ, SEQ, N_HEADS*KV_LORA,
        (long)N_HEADS*SEQ*SEQ, (long)SEQ*SEQ,
        (long)KV_LORA*SEQ, 0,
        (long)SEQ*N_HEADS*KV_LORA, KV_LORA,
        N_HEADS, 1.f, 2);

    // 11. o2 = attno @ wkvb_v^T  (batched h)
    gemm_bf3<1><<<dim3(ROWS/128, V_HEAD/128, N_HEADS), blk, SMEM_BYTES>>>(
        ath, atl, wkvbh + (size_t)NOPE*KV_LORA, wkvbl + (size_t)NOPE*KV_LORA,
        nullptr, o2h, o2l,
        ROWS, V_HEAD, KV_LORA, N_HEADS*KV_LORA, KV_LORA, DIM,
        0, KV_LORA, 0, (long)256*KV_LORA, 0, V_HEAD, N_HEADS, 1.f, 2 * 0);

    // 12. out = o2 @ wo^T  (f32 out)
    gemm_bf3<0><<<dim3(ROWS/128, DIM/128, 1), blk, SMEM_BYTES>>>(
        o2h, o2l, woh, wol, out, nullptr, nullptr,
        ROWS, DIM, DIM, DIM, DIM, DIM, 0,0, 0,0, 0,0, 1, 1.f, 0);
}